// round 2
// baseline (speedup 1.0000x reference)
#include <cuda_runtime.h>
#include <math.h>

// ---------------- problem constants ----------------
#define NS     4      // S
#define NBATCH 32     // B
#define NCIN   128
#define NCOUT  256
#define HH     16
#define WW     16
#define DDIM   1152   // CIN*3*3
#define NPIX   256    // H*W
#define NCOLS  8192   // B * NPIX
#define NBLK   9      // DDIM / 128

// ---------------- scratch (device globals, allowed) ----------------
__device__ float g_P   [(size_t)NS * DDIM * NCOLS];   // 151 MB : weighted patches, (s, d, n)
__device__ float g_Yt  [(size_t)NCOUT * NCOLS];       // 8 MB   : weighted targets, (c, n)
__device__ float g_prec[(size_t)NS * DDIM * DDIM];    // 21 MB  : prec -> Cholesky factor (lower)
__device__ float g_R   [(size_t)NS * DDIM * NCOUT];   // 4.7 MB : XLY -> solve RHS -> Wm^T
__device__ float g_Dinv[(size_t)NS * NBLK * 128 * 128];// inverse of diagonal Cholesky blocks
__device__ float g_logdet_part[NS * NBLK];
__device__ float g_part[NS * 1152];                    // per-block partial sums (deterministic)

// ---------------- patch build ----------------
__global__ __launch_bounds__(256) void build_patches(const float* __restrict__ X,
                                                     const float* __restrict__ lp) {
    size_t i = (size_t)blockIdx.x * 256 + threadIdx.x;  // over NS*DDIM*NCOLS
    int n = (int)(i % NCOLS);
    size_t r = i / NCOLS;
    int d = (int)(r % DDIM);
    int s = (int)(r / DDIM);
    int b = n >> 8;
    int p = n & 255;
    int y = p >> 4, x = p & 15;
    int cin = d / 9;
    int rem = d - cin * 9;
    int kh = rem / 3, kw = rem - kh * 3;
    int yy = y + kh - 1, xx = x + kw - 1;
    float v = 0.0f;
    if (yy >= 0 && yy < HH && xx >= 0 && xx < WW) {
        float sp = expf(0.5f * lp[b]);
        v = sp * X[((((size_t)s * NBATCH + b) * NCIN + cin) * HH + yy) * WW + xx];
    }
    g_P[i] = v;
}

__global__ __launch_bounds__(256) void build_yt(const float* __restrict__ u,
                                                const float* __restrict__ lp) {
    size_t i = (size_t)blockIdx.x * 256 + threadIdx.x;  // over NCOUT*NCOLS
    int n = (int)(i % NCOLS);
    int c = (int)(i / NCOLS);
    int b = n >> 8;
    int p = n & 255;
    g_Yt[i] = expf(0.5f * lp[b]) * u[((size_t)b * NCOUT + c) * NPIX + p];
}

// ---------------- shared tile FMA core ----------------
__device__ __forceinline__ void mm_tile_compute(const float (*As)[128], const float (*Bs)[128],
                                                float acc[8][8], int tr, int tc) {
#pragma unroll
    for (int kk = 0; kk < 16; kk++) {
        float ra[8], rb[8];
        *(float4*)&ra[0] = *(const float4*)&As[kk][tr * 8];
        *(float4*)&ra[4] = *(const float4*)&As[kk][tr * 8 + 4];
        *(float4*)&rb[0] = *(const float4*)&Bs[kk][tc * 8];
        *(float4*)&rb[4] = *(const float4*)&Bs[kk][tc * 8 + 4];
#pragma unroll
        for (int a = 0; a < 8; a++)
#pragma unroll
            for (int b = 0; b < 8; b++)
                acc[a][b] = fmaf(ra[a], rb[b], acc[a][b]);
    }
}

// ---------------- big NT GEMM (C = A * B^T), K large ----------------
__device__ __forceinline__ void sgemm_nt_big(const float* __restrict__ A,
                                             const float* __restrict__ Bp,
                                             float* __restrict__ C,
                                             int lda, int ldb, int ldc, int Kdim,
                                             float prior, int gRow, int gCol) {
    __shared__ float As[16][128];
    __shared__ float Bs[16][128];
    float acc[8][8];
#pragma unroll
    for (int a = 0; a < 8; a++)
#pragma unroll
        for (int b = 0; b < 8; b++) acc[a][b] = 0.0f;
    int tid = threadIdx.x;
    int tr = tid >> 4, tc = tid & 15;

    for (int k0 = 0; k0 < Kdim; k0 += 16) {
#pragma unroll
        for (int q = 0; q < 2; q++) {
            int idx = tid + q * 256;         // 0..511
            int rr = idx >> 2;               // 0..127
            int c4 = (idx & 3) << 2;         // 0,4,8,12
            float4 va = *(const float4*)&A[(size_t)rr * lda + k0 + c4];
            As[c4 + 0][rr] = va.x; As[c4 + 1][rr] = va.y;
            As[c4 + 2][rr] = va.z; As[c4 + 3][rr] = va.w;
            float4 vb = *(const float4*)&Bp[(size_t)rr * ldb + k0 + c4];
            Bs[c4 + 0][rr] = vb.x; Bs[c4 + 1][rr] = vb.y;
            Bs[c4 + 2][rr] = vb.z; Bs[c4 + 3][rr] = vb.w;
        }
        __syncthreads();
        mm_tile_compute(As, Bs, acc, tr, tc);
        __syncthreads();
    }
#pragma unroll
    for (int a = 0; a < 8; a++) {
        int row = tr * 8 + a;
#pragma unroll
        for (int b = 0; b < 8; b++) {
            int col = tc * 8 + b;
            float v = acc[a][b];
            if (prior != 0.0f && (gRow + row) == (gCol + col)) v += prior;
            C[(size_t)row * ldc + col] = v;
        }
    }
}

// XLX (lower tiles only, +I on diagonal)
__global__ __launch_bounds__(256) void xlx_kernel() {
    int s = blockIdx.z;
    int t = blockIdx.x;               // 0..44
    int bi = 0;
    while ((bi + 1) * (bi + 2) / 2 <= t) bi++;
    int bj = t - bi * (bi + 1) / 2;
    const float* A  = g_P + ((size_t)s * DDIM + bi * 128) * NCOLS;
    const float* Bp = g_P + ((size_t)s * DDIM + bj * 128) * NCOLS;
    float* C = g_prec + (size_t)s * DDIM * DDIM + (size_t)bi * 128 * DDIM + bj * 128;
    sgemm_nt_big(A, Bp, C, NCOLS, NCOLS, DDIM, NCOLS,
                 (bi == bj) ? 1.0f : 0.0f, bi * 128, bj * 128);
}

// XLY
__global__ __launch_bounds__(256) void xly_kernel() {
    int s = blockIdx.z;
    int bi = blockIdx.x;              // 0..8
    int bj = blockIdx.y;              // 0..1
    const float* A  = g_P + ((size_t)s * DDIM + bi * 128) * NCOLS;
    const float* Bp = g_Yt + (size_t)bj * 128 * NCOLS;
    float* C = g_R + (size_t)s * DDIM * NCOUT + (size_t)bi * 128 * NCOUT + bj * 128;
    sgemm_nt_big(A, Bp, C, NCOLS, NCOLS, NCOUT, NCOLS, 0.0f, 0, 0);
}

// ---------------- small 128x128xK=128 GEMM: C = beta*C + alpha * opA(A) @ opB(B) ----------------
template <int TA, int TB>
__device__ __forceinline__ void gemm128(const float* __restrict__ A, int lda,
                                        const float* __restrict__ Bp, int ldb,
                                        float* __restrict__ C, int ldc,
                                        float alpha, int beta) {
    __shared__ float As[16][128];
    __shared__ float Bs[16][128];
    float acc[8][8];
#pragma unroll
    for (int a = 0; a < 8; a++)
#pragma unroll
        for (int b = 0; b < 8; b++) acc[a][b] = 0.0f;
    int tid = threadIdx.x;
    int tr = tid >> 4, tc = tid & 15;

    for (int k0 = 0; k0 < 128; k0 += 16) {
#pragma unroll
        for (int q = 0; q < 2; q++) {
            int idx = tid + q * 256;
            if (TA) {  // As[k][m] = A[k*lda + m]
                int kk = idx >> 5, m4 = (idx & 31) << 2;
                float4 v = *(const float4*)&A[(size_t)(k0 + kk) * lda + m4];
                *(float4*)&As[kk][m4] = v;
            } else {   // As[k][m] = A[m*lda + k]
                int rr = idx >> 2, c4 = (idx & 3) << 2;
                float4 v = *(const float4*)&A[(size_t)rr * lda + k0 + c4];
                As[c4 + 0][rr] = v.x; As[c4 + 1][rr] = v.y;
                As[c4 + 2][rr] = v.z; As[c4 + 3][rr] = v.w;
            }
            if (TB) {  // Bs[k][n] = B[n*ldb + k]   (i.e. B transposed: NT)
                int rr = idx >> 2, c4 = (idx & 3) << 2;
                float4 v = *(const float4*)&Bp[(size_t)rr * ldb + k0 + c4];
                Bs[c4 + 0][rr] = v.x; Bs[c4 + 1][rr] = v.y;
                Bs[c4 + 2][rr] = v.z; Bs[c4 + 3][rr] = v.w;
            } else {   // Bs[k][n] = B[k*ldb + n]
                int kk = idx >> 5, m4 = (idx & 31) << 2;
                float4 v = *(const float4*)&Bp[(size_t)(k0 + kk) * ldb + m4];
                *(float4*)&Bs[kk][m4] = v;
            }
        }
        __syncthreads();
        mm_tile_compute(As, Bs, acc, tr, tc);
        __syncthreads();
    }
#pragma unroll
    for (int a = 0; a < 8; a++) {
        int row = tr * 8 + a;
#pragma unroll
        for (int b = 0; b < 8; b++) {
            int col = tc * 8 + b;
            float v = alpha * acc[a][b];
            if (beta) v += C[(size_t)row * ldc + col];
            C[(size_t)row * ldc + col] = v;
        }
    }
}

// ---------------- Cholesky: diag-block factor + explicit triangular inverse ----------------
__global__ void potf2_kernel(int kb) {
    extern __shared__ float sh[];
    float (*Ls)[129] = (float(*)[129])sh;
    float (*Iv)[129] = (float(*)[129])(sh + 128 * 129);
    __shared__ float red[128];
    int s = blockIdx.x;
    int tid = threadIdx.x;  // 128 threads
    float* Ablk = g_prec + (size_t)s * DDIM * DDIM + (size_t)kb * 128 * DDIM + kb * 128;

    for (int idx = tid; idx < 128 * 128; idx += 128) {
        int rr = idx >> 7, cc = idx & 127;
        Ls[rr][cc] = Ablk[(size_t)rr * DDIM + cc];
    }
    __syncthreads();

    // unblocked right-looking Cholesky in SMEM (lower triangle)
    for (int j = 0; j < 128; j++) {
        if (tid == j) Ls[j][j] = sqrtf(Ls[j][j]);
        __syncthreads();
        float dinv = 1.0f / Ls[j][j];
        if (tid > j) Ls[tid][j] *= dinv;
        __syncthreads();
        if (tid > j) {
            float lij = Ls[tid][j];
            for (int cc = j + 1; cc < 128; cc++) {
                if (tid >= cc) Ls[tid][cc] -= lij * Ls[cc][j];  // Ls[cc][j] broadcast
            }
        }
        __syncthreads();
    }

    // logdet partial (deterministic per (s,kb))
    red[tid] = 2.0f * logf(Ls[tid][tid]);
    __syncthreads();
    for (int off = 64; off; off >>= 1) {
        if (tid < off) red[tid] += red[tid + off];
        __syncthreads();
    }
    if (tid == 0) g_logdet_part[s * NBLK + kb] = red[0];

    // write back factored block
    for (int idx = tid; idx < 128 * 128; idx += 128) {
        int rr = idx >> 7, cc = idx & 127;
        Ablk[(size_t)rr * DDIM + cc] = Ls[rr][cc];
    }

    // explicit inverse of the (lower-triangular) block; thread = column c
    int c = tid;
    int t0 = c & ~31;  // warp-uniform start
    for (int i = 0; i < 128; i++) {
        float v = (i == c) ? 1.0f : 0.0f;
        for (int t = t0; t < i; t++) {
            float xt = (t >= c) ? Iv[t][c] : 0.0f;
            v -= Ls[i][t] * xt;  // Ls[i][t] broadcast
        }
        v = (i >= c) ? v / Ls[i][i] : 0.0f;
        Iv[i][c] = v;
    }
    __syncthreads();
    float* Dst = g_Dinv + ((size_t)s * NBLK + kb) * 128 * 128;
    for (int idx = tid; idx < 128 * 128; idx += 128) {
        int rr = idx >> 7, cc = idx & 127;
        Dst[idx] = Iv[rr][cc];
    }
}

// panel: A[i][k] = A[i][k] @ inv(Lkk)^T
__global__ __launch_bounds__(256) void chol_trsm_kernel(int k) {
    int s = blockIdx.z;
    int i = k + 1 + blockIdx.x;
    float* Ablk = g_prec + (size_t)s * DDIM * DDIM + (size_t)i * 128 * DDIM + k * 128;
    const float* Dinv = g_Dinv + ((size_t)s * NBLK + k) * 128 * 128;
    gemm128<0, 1>(Ablk, DDIM, Dinv, 128, Ablk, DDIM, 1.0f, 0);
}

// trailing: C[i][j] -= A[i][k] @ A[j][k]^T   (k < j <= i)
__global__ __launch_bounds__(256) void chol_syrk_kernel(int k) {
    int s = blockIdx.z;
    int t = blockIdx.x;
    int a = 0;
    while ((a + 1) * (a + 2) / 2 <= t) a++;
    int b = t - a * (a + 1) / 2;
    int i = k + 1 + a, j = k + 1 + b;
    const float* Aik = g_prec + (size_t)s * DDIM * DDIM + (size_t)i * 128 * DDIM + k * 128;
    const float* Ajk = g_prec + (size_t)s * DDIM * DDIM + (size_t)j * 128 * DDIM + k * 128;
    float* Cij = g_prec + (size_t)s * DDIM * DDIM + (size_t)i * 128 * DDIM + j * 128;
    gemm128<0, 1>(Aik, DDIM, Ajk, DDIM, Cij, DDIM, -1.0f, 1);
}

// ---------------- triangular solves on RHS (D x COUT per s) ----------------
__global__ __launch_bounds__(256) void fsolve_diag_kernel(int k) {
    int s = blockIdx.z;
    int ct = blockIdx.x;  // 0..1
    float* Rk = g_R + (size_t)s * DDIM * NCOUT + (size_t)k * 128 * NCOUT + ct * 128;
    const float* Dinv = g_Dinv + ((size_t)s * NBLK + k) * 128 * 128;
    gemm128<0, 0>(Dinv, 128, Rk, NCOUT, Rk, NCOUT, 1.0f, 0);
}

__global__ __launch_bounds__(256) void fsolve_update_kernel(int k) {
    int s = blockIdx.z;
    int ct = blockIdx.x;
    int i = k + 1 + blockIdx.y;
    const float* A = g_prec + (size_t)s * DDIM * DDIM + (size_t)i * 128 * DDIM + k * 128;
    const float* Rk = g_R + (size_t)s * DDIM * NCOUT + (size_t)k * 128 * NCOUT + ct * 128;
    float* Ri = g_R + (size_t)s * DDIM * NCOUT + (size_t)i * 128 * NCOUT + ct * 128;
    gemm128<0, 0>(A, DDIM, Rk, NCOUT, Ri, NCOUT, -1.0f, 1);
}

__global__ __launch_bounds__(256) void addz_kernel(const float* __restrict__ Z) {
    size_t i = (size_t)blockIdx.x * 256 + threadIdx.x;  // over NS*DDIM*NCOUT
    int c = (int)(i % NCOUT);
    size_t r = i / NCOUT;
    int d = (int)(r % DDIM);
    int s = (int)(r / DDIM);
    g_R[i] += Z[((size_t)s * NCOUT + c) * DDIM + d];
}

__global__ __launch_bounds__(256) void bsolve_diag_kernel(int k) {
    int s = blockIdx.z;
    int ct = blockIdx.x;
    float* Rk = g_R + (size_t)s * DDIM * NCOUT + (size_t)k * 128 * NCOUT + ct * 128;
    const float* Dinv = g_Dinv + ((size_t)s * NBLK + k) * 128 * 128;
    gemm128<1, 0>(Dinv, 128, Rk, NCOUT, Rk, NCOUT, 1.0f, 0);  // Dinv^T @ Rk
}

__global__ __launch_bounds__(256) void bsolve_update_kernel(int k) {
    int s = blockIdx.z;
    int ct = blockIdx.x;
    int i = blockIdx.y;  // 0..k-1
    const float* A = g_prec + (size_t)s * DDIM * DDIM + (size_t)k * 128 * DDIM + i * 128;  // L[k][i]
    const float* Rk = g_R + (size_t)s * DDIM * NCOUT + (size_t)k * 128 * NCOUT + ct * 128;
    float* Ri = g_R + (size_t)s * DDIM * NCOUT + (size_t)i * 128 * NCOUT + ct * 128;
    gemm128<1, 0>(A, DDIM, Rk, NCOUT, Ri, NCOUT, -1.0f, 1);  // -= L[k][i]^T @ Rk
}

// ---------------- output + deterministic reductions ----------------
__global__ __launch_bounds__(256) void finalize_kernel(const float* __restrict__ Z,
                                                       float* __restrict__ outW) {
    __shared__ float red[256];
    size_t i = (size_t)blockIdx.x * 256 + threadIdx.x;  // over NS*NCOUT*DDIM
    int d = (int)(i % DDIM);
    size_t r = i / DDIM;
    int c = (int)(r % NCOUT);
    int s = (int)(r / NCOUT);
    float w = g_R[((size_t)s * DDIM + d) * NCOUT + c];
    outW[i] = w;
    float z = Z[i];
    red[threadIdx.x] = 0.5f * z * z - 0.5f * w * w;
    __syncthreads();
    for (int off = 128; off; off >>= 1) {
        if (threadIdx.x < off) red[threadIdx.x] += red[threadIdx.x + off];
        __syncthreads();
    }
    if (threadIdx.x == 0) g_part[blockIdx.x] = red[0];  // blockIdx = s*1152 + j
}

__global__ __launch_bounds__(256) void logpq_kernel(float* __restrict__ outL) {
    __shared__ float red[256];
    int s = blockIdx.x;
    float acc = 0.0f;
    for (int i = threadIdx.x; i < 1152; i += 256) acc += g_part[s * 1152 + i];
    red[threadIdx.x] = acc;
    __syncthreads();
    for (int off = 128; off; off >>= 1) {
        if (threadIdx.x < off) red[threadIdx.x] += red[threadIdx.x + off];
        __syncthreads();
    }
    if (threadIdx.x == 0) {
        float ld = 0.0f;
        for (int k = 0; k < NBLK; k++) ld += g_logdet_part[s * NBLK + k];
        outL[s] = red[0] - 0.5f * (float)NCOUT * ld;
    }
}

// ---------------- launch ----------------
extern "C" void kernel_launch(void* const* d_in, const int* in_sizes, int n_in,
                              void* d_out, int out_size) {
    const float* X  = (const float*)d_in[0];
    const float* u  = (const float*)d_in[1];
    const float* lp = (const float*)d_in[2];
    const float* Z  = (const float*)d_in[3];
    float* outW = (float*)d_out;
    float* outL = outW + (size_t)NS * NCOUT * DDIM;

    cudaFuncSetAttribute(potf2_kernel, cudaFuncAttributeMaxDynamicSharedMemorySize, 135168);

    build_patches<<<147456, 256>>>(X, lp);
    build_yt<<<8192, 256>>>(u, lp);
    xlx_kernel<<<dim3(45, 1, NS), 256>>>();
    xly_kernel<<<dim3(9, 2, NS), 256>>>();

    for (int k = 0; k < NBLK; k++) {
        potf2_kernel<<<NS, 128, 2 * 128 * 129 * sizeof(float)>>>(k);
        int rem = NBLK - 1 - k;
        if (rem > 0) {
            chol_trsm_kernel<<<dim3(rem, 1, NS), 256>>>(k);
            chol_syrk_kernel<<<dim3(rem * (rem + 1) / 2, 1, NS), 256>>>(k);
        }
    }

    for (int k = 0; k < NBLK; k++) {
        fsolve_diag_kernel<<<dim3(2, 1, NS), 256>>>(k);
        if (k < NBLK - 1) fsolve_update_kernel<<<dim3(2, NBLK - 1 - k, NS), 256>>>(k);
    }
    addz_kernel<<<4608, 256>>>(Z);
    for (int k = NBLK - 1; k >= 0; k--) {
        bsolve_diag_kernel<<<dim3(2, 1, NS), 256>>>(k);
        if (k > 0) bsolve_update_kernel<<<dim3(2, k, NS), 256>>>(k);
    }

    finalize_kernel<<<4608, 256>>>(Z, outW);
    logpq_kernel<<<NS, 256>>>(outL);
}

// round 4
// speedup vs baseline: 2.3916x; 2.3916x over previous
#include <cuda_runtime.h>
#include <cuda_bf16.h>
#include <math.h>
#include <stdint.h>

// ---------------- problem constants ----------------
#define NS     4
#define NBATCH 32
#define NCIN   128
#define NCOUT  256
#define HH     16
#define WW     16
#define DDIM   1152
#define NPIX   256
#define NCOLS  8192
#define NBLK   9

// ---------------- scratch ----------------
__device__ __nv_bfloat16 g_Phi[(size_t)NS * DDIM * NCOLS];
__device__ __nv_bfloat16 g_Plo[(size_t)NS * DDIM * NCOLS];
__device__ __nv_bfloat16 g_Yhi[(size_t)NCOUT * NCOLS];
__device__ __nv_bfloat16 g_Ylo[(size_t)NCOUT * NCOLS];
__device__ float g_prec[(size_t)NS * DDIM * DDIM];
__device__ float g_R   [(size_t)NS * DDIM * NCOUT];
__device__ float g_Dinv[(size_t)NS * NBLK * 128 * 128];
__device__ float g_logdet_part[NS * NBLK];
__device__ float g_part[NS * 1152];

// ---------------- helpers ----------------
__device__ __forceinline__ uint32_t smem_u32(const void* p) {
    uint32_t a;
    asm("{ .reg .u64 t; cvta.to.shared.u64 t, %1; cvt.u32.u64 %0, t; }" : "=r"(a) : "l"(p));
    return a;
}

#define CP_ASYNC16(dst, src) \
    asm volatile("cp.async.cg.shared.global [%0], [%1], 16;" :: "r"(dst), "l"(src) : "memory")
#define CP_COMMIT() asm volatile("cp.async.commit_group;" ::: "memory")
#define CP_WAIT1()  asm volatile("cp.async.wait_group 1;" ::: "memory")

#define LDMATRIX_X4(r0, r1, r2, r3, addr) \
    asm volatile("ldmatrix.sync.aligned.m8n8.x4.shared.b16 {%0,%1,%2,%3}, [%4];" \
        : "=r"(r0), "=r"(r1), "=r"(r2), "=r"(r3) : "r"(addr))

#define MMA16816(d, a, b0, b1) \
    asm volatile("mma.sync.aligned.m16n8k16.row.col.f32.bf16.bf16.f32 " \
        "{%0,%1,%2,%3}, {%4,%5,%6,%7}, {%8,%9}, {%0,%1,%2,%3};" \
        : "+f"((d)[0]), "+f"((d)[1]), "+f"((d)[2]), "+f"((d)[3]) \
        : "r"((a)[0]), "r"((a)[1]), "r"((a)[2]), "r"((a)[3]), "r"(b0), "r"(b1))

__device__ __forceinline__ uint32_t sw128(uint32_t off) {
    return off ^ ((off >> 3) & 0x70);
}

// ---------------- patch build (bf16 hi/lo) ----------------
__global__ __launch_bounds__(256) void build_patches(const float* __restrict__ X,
                                                     const float* __restrict__ lp) {
    size_t i = (size_t)blockIdx.x * 256 + threadIdx.x;
    int n = (int)(i % NCOLS);
    size_t r = i / NCOLS;
    int d = (int)(r % DDIM);
    int s = (int)(r / DDIM);
    int b = n >> 8;
    int p = n & 255;
    int y = p >> 4, x = p & 15;
    int cin = d / 9;
    int rem = d - cin * 9;
    int kh = rem / 3, kw = rem - kh * 3;
    int yy = y + kh - 1, xx = x + kw - 1;
    float v = 0.0f;
    if (yy >= 0 && yy < HH && xx >= 0 && xx < WW) {
        float sp = expf(0.5f * lp[b]);
        v = sp * X[((((size_t)s * NBATCH + b) * NCIN + cin) * HH + yy) * WW + xx];
    }
    __nv_bfloat16 hi = __float2bfloat16_rn(v);
    g_Phi[i] = hi;
    g_Plo[i] = __float2bfloat16_rn(v - __bfloat162float(hi));
}

__global__ __launch_bounds__(256) void build_yt(const float* __restrict__ u,
                                                const float* __restrict__ lp) {
    size_t i = (size_t)blockIdx.x * 256 + threadIdx.x;
    int n = (int)(i % NCOLS);
    int c = (int)(i / NCOLS);
    int b = n >> 8;
    int p = n & 255;
    float v = expf(0.5f * lp[b]) * u[((size_t)b * NCOUT + c) * NPIX + p];
    __nv_bfloat16 hi = __float2bfloat16_rn(v);
    g_Yhi[i] = hi;
    g_Ylo[i] = __float2bfloat16_rn(v - __bfloat162float(hi));
}

// ---------------- warp-MMA Gram kernel (XLX lower tiles + XLY) ----------------
// C(128x128) = A(128xK) @ B(128xK)^T, hi/lo bf16 split (3 products), K = 8192.
// 256 threads = 8 warps (4 M x 2 N), warp tile 32x64.
// SMEM: double buffer, each buffer = Ah|Al|Bh|Bl tiles of 128x64 bf16 (16KB each).
#define TILE_B 16384
#define BUF_B  65536
#define GRAM_SMEM (2 * BUF_B)

__global__ __launch_bounds__(256, 1) void tc_gram_kernel() {
    extern __shared__ char sm[];
    uint32_t smb = smem_u32(sm);
    int tid = threadIdx.x;
    int wid = tid >> 5, lid = tid & 31;
    int s = blockIdx.y;
    int t = blockIdx.x;

    const __nv_bfloat16 *Ah, *Al, *Bh, *Bl;
    float* C;
    int ldc;
    float prior;
    if (t < 45) {
        int bi = 0;
        while ((bi + 1) * (bi + 2) / 2 <= t) bi++;
        int bj = t - bi * (bi + 1) / 2;
        size_t ar = (size_t)(s * DDIM + bi * 128) * NCOLS;
        size_t br = (size_t)(s * DDIM + bj * 128) * NCOLS;
        Ah = g_Phi + ar; Al = g_Plo + ar;
        Bh = g_Phi + br; Bl = g_Plo + br;
        C = g_prec + (size_t)s * DDIM * DDIM + (size_t)bi * 128 * DDIM + bj * 128;
        ldc = DDIM;
        prior = (bi == bj) ? 1.0f : 0.0f;
    } else {
        int u2 = t - 45;
        int bi = u2 >> 1, bj = u2 & 1;
        size_t ar = (size_t)(s * DDIM + bi * 128) * NCOLS;
        size_t br = (size_t)bj * 128 * NCOLS;
        Ah = g_Phi + ar; Al = g_Plo + ar;
        Bh = g_Yhi + br; Bl = g_Ylo + br;
        C = g_R + (size_t)s * DDIM * NCOUT + (size_t)bi * 128 * NCOUT + bj * 128;
        ldc = NCOUT;
        prior = 0.0f;
    }

    // per-thread load mapping: 4 rows of 16B per array per chunk
    int lrow[4], lseg[4];
    uint32_t lsw[4];
#pragma unroll
    for (int j = 0; j < 4; j++) {
        int idx = tid + j * 256;       // 0..1023
        lrow[j] = idx >> 3;
        lseg[j] = idx & 7;
        lsw[j] = sw128((uint32_t)(lrow[j] * 128 + lseg[j] * 16));
    }

    float acc[2][8][4];
#pragma unroll
    for (int a = 0; a < 2; a++)
#pragma unroll
        for (int b = 0; b < 8; b++)
#pragma unroll
            for (int c = 0; c < 4; c++) acc[a][b][c] = 0.0f;

    int wm = (wid >> 1) * 32;   // warp row offset
    int wn = (wid & 1) * 64;    // warp col offset

    // ldmatrix lane address components (row/kseg within tile)
    int l16 = lid & 15;
    int kseg16 = (lid >> 4) * 16;   // 0 or 16 bytes

    // prologue: load chunk 0 into buf 0
    {
        const __nv_bfloat16* g0 = Ah;
#pragma unroll
        for (int arr = 0; arr < 4; arr++) {
            const __nv_bfloat16* G = (arr == 0) ? Ah : (arr == 1) ? Al : (arr == 2) ? Bh : Bl;
#pragma unroll
            for (int j = 0; j < 4; j++)
                CP_ASYNC16(smb + arr * TILE_B + lsw[j],
                           G + (size_t)lrow[j] * NCOLS + lseg[j] * 8);
        }
        (void)g0;
        CP_COMMIT();
    }

    for (int i = 0; i < 128; i++) {
        int buf = i & 1;
        if (i + 1 < 128) {
            int k0 = (i + 1) * 64;
            uint32_t bb = smb + ((i + 1) & 1) * BUF_B;
#pragma unroll
            for (int arr = 0; arr < 4; arr++) {
                const __nv_bfloat16* G = (arr == 0) ? Ah : (arr == 1) ? Al : (arr == 2) ? Bh : Bl;
#pragma unroll
                for (int j = 0; j < 4; j++)
                    CP_ASYNC16(bb + arr * TILE_B + lsw[j],
                               G + (size_t)lrow[j] * NCOLS + k0 + lseg[j] * 8);
            }
        }
        CP_COMMIT();
        CP_WAIT1();
        __syncthreads();

        uint32_t base = smb + buf * BUF_B;
#pragma unroll
        for (int ks = 0; ks < 4; ks++) {
            int kb = ks * 32 + kseg16;
            uint32_t ah[2][4], al[2][4], bh[4][4], bl[4][4];
#pragma unroll
            for (int mb = 0; mb < 2; mb++) {
                uint32_t off = sw128((uint32_t)((wm + mb * 16 + l16) * 128 + kb));
                LDMATRIX_X4(ah[mb][0], ah[mb][1], ah[mb][2], ah[mb][3], base + off);
                LDMATRIX_X4(al[mb][0], al[mb][1], al[mb][2], al[mb][3], base + TILE_B + off);
            }
#pragma unroll
            for (int nb = 0; nb < 4; nb++) {
                uint32_t off = sw128((uint32_t)((wn + nb * 16 + l16) * 128 + kb));
                LDMATRIX_X4(bh[nb][0], bh[nb][1], bh[nb][2], bh[nb][3], base + 2 * TILE_B + off);
                LDMATRIX_X4(bl[nb][0], bl[nb][1], bl[nb][2], bl[nb][3], base + 3 * TILE_B + off);
            }
#pragma unroll
            for (int mb = 0; mb < 2; mb++)
#pragma unroll
                for (int n8 = 0; n8 < 8; n8++) {
                    int nb = n8 >> 1, h = n8 & 1;
                    MMA16816(acc[mb][n8], ah[mb], bh[nb][h], bh[nb][h + 2]);
                    MMA16816(acc[mb][n8], ah[mb], bl[nb][h], bl[nb][h + 2]);
                    MMA16816(acc[mb][n8], al[mb], bh[nb][h], bh[nb][h + 2]);
                }
        }
        __syncthreads();
    }

    // epilogue
    int tq = lid >> 2;           // 0..7
    int tc2 = (lid & 3) * 2;     // 0,2,4,6
#pragma unroll
    for (int mb = 0; mb < 2; mb++) {
#pragma unroll
        for (int n8 = 0; n8 < 8; n8++) {
            int col = wn + n8 * 8 + tc2;
            int row0 = wm + mb * 16 + tq;
            int row1 = row0 + 8;
            float c0 = acc[mb][n8][0], c1 = acc[mb][n8][1];
            float c2 = acc[mb][n8][2], c3 = acc[mb][n8][3];
            if (prior != 0.0f) {
                if (row0 == col) c0 += prior;
                if (row0 == col + 1) c1 += prior;
                if (row1 == col) c2 += prior;
                if (row1 == col + 1) c3 += prior;
            }
            *(float2*)&C[(size_t)row0 * ldc + col] = make_float2(c0, c1);
            *(float2*)&C[(size_t)row1 * ldc + col] = make_float2(c2, c3);
        }
    }
}

// ---------------- fp32 tile FMA core (Cholesky/solve GEMMs) ----------------
__device__ __forceinline__ void mm_tile_compute(const float (*As)[128], const float (*Bs)[128],
                                                float acc[8][8], int tr, int tc) {
#pragma unroll
    for (int kk = 0; kk < 16; kk++) {
        float ra[8], rb[8];
        *(float4*)&ra[0] = *(const float4*)&As[kk][tr * 8];
        *(float4*)&ra[4] = *(const float4*)&As[kk][tr * 8 + 4];
        *(float4*)&rb[0] = *(const float4*)&Bs[kk][tc * 8];
        *(float4*)&rb[4] = *(const float4*)&Bs[kk][tc * 8 + 4];
#pragma unroll
        for (int a = 0; a < 8; a++)
#pragma unroll
            for (int b = 0; b < 8; b++)
                acc[a][b] = fmaf(ra[a], rb[b], acc[a][b]);
    }
}

template <int TA, int TB>
__device__ __forceinline__ void gemm128(const float* __restrict__ A, int lda,
                                        const float* __restrict__ Bp, int ldb,
                                        float* __restrict__ C, int ldc,
                                        float alpha, int beta) {
    __shared__ float As[16][128];
    __shared__ float Bs[16][128];
    float acc[8][8];
#pragma unroll
    for (int a = 0; a < 8; a++)
#pragma unroll
        for (int b = 0; b < 8; b++) acc[a][b] = 0.0f;
    int tid = threadIdx.x;
    int tr = tid >> 4, tc = tid & 15;

    for (int k0 = 0; k0 < 128; k0 += 16) {
#pragma unroll
        for (int q = 0; q < 2; q++) {
            int idx = tid + q * 256;
            if (TA) {
                int kk = idx >> 5, m4 = (idx & 31) << 2;
                float4 v = *(const float4*)&A[(size_t)(k0 + kk) * lda + m4];
                *(float4*)&As[kk][m4] = v;
            } else {
                int rr = idx >> 2, c4 = (idx & 3) << 2;
                float4 v = *(const float4*)&A[(size_t)rr * lda + k0 + c4];
                As[c4 + 0][rr] = v.x; As[c4 + 1][rr] = v.y;
                As[c4 + 2][rr] = v.z; As[c4 + 3][rr] = v.w;
            }
            if (TB) {
                int rr = idx >> 2, c4 = (idx & 3) << 2;
                float4 v = *(const float4*)&Bp[(size_t)rr * ldb + k0 + c4];
                Bs[c4 + 0][rr] = v.x; Bs[c4 + 1][rr] = v.y;
                Bs[c4 + 2][rr] = v.z; Bs[c4 + 3][rr] = v.w;
            } else {
                int kk = idx >> 5, m4 = (idx & 31) << 2;
                float4 v = *(const float4*)&Bp[(size_t)(k0 + kk) * ldb + m4];
                *(float4*)&Bs[kk][m4] = v;
            }
        }
        __syncthreads();
        mm_tile_compute(As, Bs, acc, tr, tc);
        __syncthreads();
    }
#pragma unroll
    for (int a = 0; a < 8; a++) {
        int row = tr * 8 + a;
#pragma unroll
        for (int b = 0; b < 8; b++) {
            int col = tc * 8 + b;
            float v = alpha * acc[a][b];
            if (beta) v += C[(size_t)row * ldc + col];
            C[(size_t)row * ldc + col] = v;
        }
    }
}

// ---------------- Cholesky ----------------
__global__ void potf2_kernel(int kb) {
    extern __shared__ float sh[];
    float (*Ls)[129] = (float(*)[129])sh;
    float (*Iv)[129] = (float(*)[129])(sh + 128 * 129);
    __shared__ float red[128];
    int s = blockIdx.x;
    int tid = threadIdx.x;
    float* Ablk = g_prec + (size_t)s * DDIM * DDIM + (size_t)kb * 128 * DDIM + kb * 128;

    for (int idx = tid; idx < 128 * 128; idx += 128) {
        int rr = idx >> 7, cc = idx & 127;
        Ls[rr][cc] = Ablk[(size_t)rr * DDIM + cc];
    }
    __syncthreads();

    for (int j = 0; j < 128; j++) {
        if (tid == j) Ls[j][j] = sqrtf(Ls[j][j]);
        __syncthreads();
        float dinv = 1.0f / Ls[j][j];
        if (tid > j) Ls[tid][j] *= dinv;
        __syncthreads();
        if (tid > j) {
            float lij = Ls[tid][j];
            for (int cc = j + 1; cc < 128; cc++) {
                if (tid >= cc) Ls[tid][cc] -= lij * Ls[cc][j];
            }
        }
        __syncthreads();
    }

    red[tid] = 2.0f * logf(Ls[tid][tid]);
    __syncthreads();
    for (int off = 64; off; off >>= 1) {
        if (tid < off) red[tid] += red[tid + off];
        __syncthreads();
    }
    if (tid == 0) g_logdet_part[s * NBLK + kb] = red[0];

    for (int idx = tid; idx < 128 * 128; idx += 128) {
        int rr = idx >> 7, cc = idx & 127;
        Ablk[(size_t)rr * DDIM + cc] = Ls[rr][cc];
    }

    int c = tid;
    int t0 = c & ~31;
    for (int i = 0; i < 128; i++) {
        float v = (i == c) ? 1.0f : 0.0f;
        for (int t = t0; t < i; t++) {
            float xt = (t >= c) ? Iv[t][c] : 0.0f;
            v -= Ls[i][t] * xt;
        }
        v = (i >= c) ? v / Ls[i][i] : 0.0f;
        Iv[i][c] = v;
    }
    __syncthreads();
    float* Dst = g_Dinv + ((size_t)s * NBLK + kb) * 128 * 128;
    for (int idx = tid; idx < 128 * 128; idx += 128) {
        int rr = idx >> 7, cc = idx & 127;
        Dst[idx] = Iv[rr][cc];
    }
}

__global__ __launch_bounds__(256) void chol_trsm_kernel(int k) {
    int s = blockIdx.z;
    int i = k + 1 + blockIdx.x;
    float* Ablk = g_prec + (size_t)s * DDIM * DDIM + (size_t)i * 128 * DDIM + k * 128;
    const float* Dinv = g_Dinv + ((size_t)s * NBLK + k) * 128 * 128;
    gemm128<0, 1>(Ablk, DDIM, Dinv, 128, Ablk, DDIM, 1.0f, 0);
}

__global__ __launch_bounds__(256) void chol_syrk_kernel(int k) {
    int s = blockIdx.z;
    int t = blockIdx.x;
    int a = 0;
    while ((a + 1) * (a + 2) / 2 <= t) a++;
    int b = t - a * (a + 1) / 2;
    int i = k + 1 + a, j = k + 1 + b;
    const float* Aik = g_prec + (size_t)s * DDIM * DDIM + (size_t)i * 128 * DDIM + k * 128;
    const float* Ajk = g_prec + (size_t)s * DDIM * DDIM + (size_t)j * 128 * DDIM + k * 128;
    float* Cij = g_prec + (size_t)s * DDIM * DDIM + (size_t)i * 128 * DDIM + j * 128;
    gemm128<0, 1>(Aik, DDIM, Ajk, DDIM, Cij, DDIM, -1.0f, 1);
}

// ---------------- triangular solves ----------------
__global__ __launch_bounds__(256) void fsolve_diag_kernel(int k) {
    int s = blockIdx.z;
    int ct = blockIdx.x;
    float* Rk = g_R + (size_t)s * DDIM * NCOUT + (size_t)k * 128 * NCOUT + ct * 128;
    const float* Dinv = g_Dinv + ((size_t)s * NBLK + k) * 128 * 128;
    gemm128<0, 0>(Dinv, 128, Rk, NCOUT, Rk, NCOUT, 1.0f, 0);
}

__global__ __launch_bounds__(256) void fsolve_update_kernel(int k) {
    int s = blockIdx.z;
    int ct = blockIdx.x;
    int i = k + 1 + blockIdx.y;
    const float* A = g_prec + (size_t)s * DDIM * DDIM + (size_t)i * 128 * DDIM + k * 128;
    const float* Rk = g_R + (size_t)s * DDIM * NCOUT + (size_t)k * 128 * NCOUT + ct * 128;
    float* Ri = g_R + (size_t)s * DDIM * NCOUT + (size_t)i * 128 * NCOUT + ct * 128;
    gemm128<0, 0>(A, DDIM, Rk, NCOUT, Ri, NCOUT, -1.0f, 1);
}

__global__ __launch_bounds__(256) void addz_kernel(const float* __restrict__ Z) {
    size_t i = (size_t)blockIdx.x * 256 + threadIdx.x;
    int c = (int)(i % NCOUT);
    size_t r = i / NCOUT;
    int d = (int)(r % DDIM);
    int s = (int)(r / DDIM);
    g_R[i] += Z[((size_t)s * NCOUT + c) * DDIM + d];
}

__global__ __launch_bounds__(256) void bsolve_diag_kernel(int k) {
    int s = blockIdx.z;
    int ct = blockIdx.x;
    float* Rk = g_R + (size_t)s * DDIM * NCOUT + (size_t)k * 128 * NCOUT + ct * 128;
    const float* Dinv = g_Dinv + ((size_t)s * NBLK + k) * 128 * 128;
    gemm128<1, 0>(Dinv, 128, Rk, NCOUT, Rk, NCOUT, 1.0f, 0);
}

__global__ __launch_bounds__(256) void bsolve_update_kernel(int k) {
    int s = blockIdx.z;
    int ct = blockIdx.x;
    int i = blockIdx.y;
    const float* A = g_prec + (size_t)s * DDIM * DDIM + (size_t)k * 128 * DDIM + i * 128;
    const float* Rk = g_R + (size_t)s * DDIM * NCOUT + (size_t)k * 128 * NCOUT + ct * 128;
    float* Ri = g_R + (size_t)s * DDIM * NCOUT + (size_t)i * 128 * NCOUT + ct * 128;
    gemm128<1, 0>(A, DDIM, Rk, NCOUT, Ri, NCOUT, -1.0f, 1);
}

// ---------------- output + reductions ----------------
__global__ __launch_bounds__(256) void finalize_kernel(const float* __restrict__ Z,
                                                       float* __restrict__ outW) {
    __shared__ float red[256];
    size_t i = (size_t)blockIdx.x * 256 + threadIdx.x;
    int d = (int)(i % DDIM);
    size_t r = i / DDIM;
    int c = (int)(r % NCOUT);
    int s = (int)(r / NCOUT);
    float w = g_R[((size_t)s * DDIM + d) * NCOUT + c];
    outW[i] = w;
    float z = Z[i];
    red[threadIdx.x] = 0.5f * z * z - 0.5f * w * w;
    __syncthreads();
    for (int off = 128; off; off >>= 1) {
        if (threadIdx.x < off) red[threadIdx.x] += red[threadIdx.x + off];
        __syncthreads();
    }
    if (threadIdx.x == 0) g_part[blockIdx.x] = red[0];
}

__global__ __launch_bounds__(256) void logpq_kernel(float* __restrict__ outL) {
    __shared__ float red[256];
    int s = blockIdx.x;
    float acc = 0.0f;
    for (int i = threadIdx.x; i < 1152; i += 256) acc += g_part[s * 1152 + i];
    red[threadIdx.x] = acc;
    __syncthreads();
    for (int off = 128; off; off >>= 1) {
        if (threadIdx.x < off) red[threadIdx.x] += red[threadIdx.x + off];
        __syncthreads();
    }
    if (threadIdx.x == 0) {
        float ld = 0.0f;
        for (int k = 0; k < NBLK; k++) ld += g_logdet_part[s * NBLK + k];
        outL[s] = red[0] - 0.5f * (float)NCOUT * ld;
    }
}

// ---------------- launch ----------------
extern "C" void kernel_launch(void* const* d_in, const int* in_sizes, int n_in,
                              void* d_out, int out_size) {
    const float* X  = (const float*)d_in[0];
    const float* u  = (const float*)d_in[1];
    const float* lp = (const float*)d_in[2];
    const float* Z  = (const float*)d_in[3];
    float* outW = (float*)d_out;
    float* outL = outW + (size_t)NS * NCOUT * DDIM;

    cudaFuncSetAttribute(potf2_kernel, cudaFuncAttributeMaxDynamicSharedMemorySize, 135168);
    cudaFuncSetAttribute(tc_gram_kernel, cudaFuncAttributeMaxDynamicSharedMemorySize, GRAM_SMEM);

    build_patches<<<147456, 256>>>(X, lp);
    build_yt<<<8192, 256>>>(u, lp);
    tc_gram_kernel<<<dim3(63, NS), 256, GRAM_SMEM>>>();

    for (int k = 0; k < NBLK; k++) {
        potf2_kernel<<<NS, 128, 2 * 128 * 129 * sizeof(float)>>>(k);
        int rem = NBLK - 1 - k;
        if (rem > 0) {
            chol_trsm_kernel<<<dim3(rem, 1, NS), 256>>>(k);
            chol_syrk_kernel<<<dim3(rem * (rem + 1) / 2, 1, NS), 256>>>(k);
        }
    }

    for (int k = 0; k < NBLK; k++) {
        fsolve_diag_kernel<<<dim3(2, 1, NS), 256>>>(k);
        if (k < NBLK - 1) fsolve_update_kernel<<<dim3(2, NBLK - 1 - k, NS), 256>>>(k);
    }
    addz_kernel<<<4608, 256>>>(Z);
    for (int k = NBLK - 1; k >= 0; k--) {
        bsolve_diag_kernel<<<dim3(2, 1, NS), 256>>>(k);
        if (k > 0) bsolve_update_kernel<<<dim3(2, k, NS), 256>>>(k);
    }

    finalize_kernel<<<4608, 256>>>(Z, outW);
    logpq_kernel<<<NS, 256>>>(outL);
}

// round 5
// speedup vs baseline: 3.0553x; 1.2775x over previous
#include <cuda_runtime.h>
#include <cuda_bf16.h>
#include <math.h>
#include <stdint.h>

// ---------------- problem constants ----------------
#define NS     4
#define NBATCH 32
#define NCIN   128
#define NCOUT  256
#define HH     16
#define WW     16
#define DDIM   1152
#define NPIX   256
#define NCOLS  8192
#define NBLK   9

// ---------------- scratch ----------------
__device__ __nv_bfloat16 g_Phi[(size_t)NS * DDIM * NCOLS];
__device__ __nv_bfloat16 g_Plo[(size_t)NS * DDIM * NCOLS];
__device__ __nv_bfloat16 g_Yhi[(size_t)NCOUT * NCOLS];
__device__ __nv_bfloat16 g_Ylo[(size_t)NCOUT * NCOLS];
__device__ float g_prec[(size_t)NS * DDIM * DDIM];
__device__ float g_R   [(size_t)NS * DDIM * NCOUT];
__device__ float g_Dinv[(size_t)NS * NBLK * 128 * 128];
__device__ float g_logdet_part[NS * NBLK];
__device__ float g_part[NS * 1152];

// ---------------- helpers ----------------
__device__ __forceinline__ uint32_t smem_u32(const void* p) {
    uint32_t a;
    asm("{ .reg .u64 t; cvta.to.shared.u64 t, %1; cvt.u32.u64 %0, t; }" : "=r"(a) : "l"(p));
    return a;
}

#define CP_ASYNC16(dst, src) \
    asm volatile("cp.async.cg.shared.global [%0], [%1], 16;" :: "r"(dst), "l"(src) : "memory")
#define CP_COMMIT() asm volatile("cp.async.commit_group;" ::: "memory")
#define CP_WAIT1()  asm volatile("cp.async.wait_group 1;" ::: "memory")

#define LDMATRIX_X4(r0, r1, r2, r3, addr) \
    asm volatile("ldmatrix.sync.aligned.m8n8.x4.shared.b16 {%0,%1,%2,%3}, [%4];" \
        : "=r"(r0), "=r"(r1), "=r"(r2), "=r"(r3) : "r"(addr))

#define MMA16816(d, a, b0, b1) \
    asm volatile("mma.sync.aligned.m16n8k16.row.col.f32.bf16.bf16.f32 " \
        "{%0,%1,%2,%3}, {%4,%5,%6,%7}, {%8,%9}, {%0,%1,%2,%3};" \
        : "+f"((d)[0]), "+f"((d)[1]), "+f"((d)[2]), "+f"((d)[3]) \
        : "r"((a)[0]), "r"((a)[1]), "r"((a)[2]), "r"((a)[3]), "r"(b0), "r"(b1))

__device__ __forceinline__ uint32_t sw128(uint32_t off) {
    return off ^ ((off >> 3) & 0x70);
}

// ---------------- patch build (bf16 hi/lo) ----------------
__global__ __launch_bounds__(256) void build_patches(const float* __restrict__ X,
                                                     const float* __restrict__ lp) {
    size_t i = (size_t)blockIdx.x * 256 + threadIdx.x;
    int n = (int)(i % NCOLS);
    size_t r = i / NCOLS;
    int d = (int)(r % DDIM);
    int s = (int)(r / DDIM);
    int b = n >> 8;
    int p = n & 255;
    int y = p >> 4, x = p & 15;
    int cin = d / 9;
    int rem = d - cin * 9;
    int kh = rem / 3, kw = rem - kh * 3;
    int yy = y + kh - 1, xx = x + kw - 1;
    float v = 0.0f;
    if (yy >= 0 && yy < HH && xx >= 0 && xx < WW) {
        float sp = expf(0.5f * lp[b]);
        v = sp * X[((((size_t)s * NBATCH + b) * NCIN + cin) * HH + yy) * WW + xx];
    }
    __nv_bfloat16 hi = __float2bfloat16_rn(v);
    g_Phi[i] = hi;
    g_Plo[i] = __float2bfloat16_rn(v - __bfloat162float(hi));
}

__global__ __launch_bounds__(256) void build_yt(const float* __restrict__ u,
                                                const float* __restrict__ lp) {
    size_t i = (size_t)blockIdx.x * 256 + threadIdx.x;
    int n = (int)(i % NCOLS);
    int c = (int)(i / NCOLS);
    int b = n >> 8;
    int p = n & 255;
    float v = expf(0.5f * lp[b]) * u[((size_t)b * NCOUT + c) * NPIX + p];
    __nv_bfloat16 hi = __float2bfloat16_rn(v);
    g_Yhi[i] = hi;
    g_Ylo[i] = __float2bfloat16_rn(v - __bfloat162float(hi));
}

// ---------------- warp-MMA Gram kernel (XLX lower tiles + XLY) ----------------
#define TILE_B 16384
#define BUF_B  65536
#define GRAM_SMEM (2 * BUF_B)

__global__ __launch_bounds__(256, 1) void tc_gram_kernel() {
    extern __shared__ char sm[];
    uint32_t smb = smem_u32(sm);
    int tid = threadIdx.x;
    int wid = tid >> 5, lid = tid & 31;
    int s = blockIdx.y;
    int t = blockIdx.x;

    const __nv_bfloat16 *Ah, *Al, *Bh, *Bl;
    float* C;
    int ldc;
    float prior;
    if (t < 45) {
        int bi = 0;
        while ((bi + 1) * (bi + 2) / 2 <= t) bi++;
        int bj = t - bi * (bi + 1) / 2;
        size_t ar = (size_t)(s * DDIM + bi * 128) * NCOLS;
        size_t br = (size_t)(s * DDIM + bj * 128) * NCOLS;
        Ah = g_Phi + ar; Al = g_Plo + ar;
        Bh = g_Phi + br; Bl = g_Plo + br;
        C = g_prec + (size_t)s * DDIM * DDIM + (size_t)bi * 128 * DDIM + bj * 128;
        ldc = DDIM;
        prior = (bi == bj) ? 1.0f : 0.0f;
    } else {
        int u2 = t - 45;
        int bi = u2 >> 1, bj = u2 & 1;
        size_t ar = (size_t)(s * DDIM + bi * 128) * NCOLS;
        size_t br = (size_t)bj * 128 * NCOLS;
        Ah = g_Phi + ar; Al = g_Plo + ar;
        Bh = g_Yhi + br; Bl = g_Ylo + br;
        C = g_R + (size_t)s * DDIM * NCOUT + (size_t)bi * 128 * NCOUT + bj * 128;
        ldc = NCOUT;
        prior = 0.0f;
    }

    int lrow[4], lseg[4];
    uint32_t lsw[4];
#pragma unroll
    for (int j = 0; j < 4; j++) {
        int idx = tid + j * 256;
        lrow[j] = idx >> 3;
        lseg[j] = idx & 7;
        lsw[j] = sw128((uint32_t)(lrow[j] * 128 + lseg[j] * 16));
    }

    float acc[2][8][4];
#pragma unroll
    for (int a = 0; a < 2; a++)
#pragma unroll
        for (int b = 0; b < 8; b++)
#pragma unroll
            for (int c = 0; c < 4; c++) acc[a][b][c] = 0.0f;

    int wm = (wid >> 1) * 32;
    int wn = (wid & 1) * 64;
    int l16 = lid & 15;
    int kseg16 = (lid >> 4) * 16;

    {
#pragma unroll
        for (int arr = 0; arr < 4; arr++) {
            const __nv_bfloat16* G = (arr == 0) ? Ah : (arr == 1) ? Al : (arr == 2) ? Bh : Bl;
#pragma unroll
            for (int j = 0; j < 4; j++)
                CP_ASYNC16(smb + arr * TILE_B + lsw[j],
                           G + (size_t)lrow[j] * NCOLS + lseg[j] * 8);
        }
        CP_COMMIT();
    }

    for (int i = 0; i < 128; i++) {
        int buf = i & 1;
        if (i + 1 < 128) {
            int k0 = (i + 1) * 64;
            uint32_t bb = smb + ((i + 1) & 1) * BUF_B;
#pragma unroll
            for (int arr = 0; arr < 4; arr++) {
                const __nv_bfloat16* G = (arr == 0) ? Ah : (arr == 1) ? Al : (arr == 2) ? Bh : Bl;
#pragma unroll
                for (int j = 0; j < 4; j++)
                    CP_ASYNC16(bb + arr * TILE_B + lsw[j],
                               G + (size_t)lrow[j] * NCOLS + k0 + lseg[j] * 8);
            }
        }
        CP_COMMIT();
        CP_WAIT1();
        __syncthreads();

        uint32_t base = smb + buf * BUF_B;
#pragma unroll
        for (int ks = 0; ks < 4; ks++) {
            int kb = ks * 32 + kseg16;
            uint32_t ah[2][4], al[2][4], bh[4][4], bl[4][4];
#pragma unroll
            for (int mb = 0; mb < 2; mb++) {
                uint32_t off = sw128((uint32_t)((wm + mb * 16 + l16) * 128 + kb));
                LDMATRIX_X4(ah[mb][0], ah[mb][1], ah[mb][2], ah[mb][3], base + off);
                LDMATRIX_X4(al[mb][0], al[mb][1], al[mb][2], al[mb][3], base + TILE_B + off);
            }
#pragma unroll
            for (int nb = 0; nb < 4; nb++) {
                uint32_t off = sw128((uint32_t)((wn + nb * 16 + l16) * 128 + kb));
                LDMATRIX_X4(bh[nb][0], bh[nb][1], bh[nb][2], bh[nb][3], base + 2 * TILE_B + off);
                LDMATRIX_X4(bl[nb][0], bl[nb][1], bl[nb][2], bl[nb][3], base + 3 * TILE_B + off);
            }
#pragma unroll
            for (int mb = 0; mb < 2; mb++)
#pragma unroll
                for (int n8 = 0; n8 < 8; n8++) {
                    int nb = n8 >> 1, h = n8 & 1;
                    MMA16816(acc[mb][n8], ah[mb], bh[nb][h], bh[nb][h + 2]);
                    MMA16816(acc[mb][n8], ah[mb], bl[nb][h], bl[nb][h + 2]);
                    MMA16816(acc[mb][n8], al[mb], bh[nb][h], bh[nb][h + 2]);
                }
        }
        __syncthreads();
    }

    int tq = lid >> 2;
    int tc2 = (lid & 3) * 2;
#pragma unroll
    for (int mb = 0; mb < 2; mb++) {
#pragma unroll
        for (int n8 = 0; n8 < 8; n8++) {
            int col = wn + n8 * 8 + tc2;
            int row0 = wm + mb * 16 + tq;
            int row1 = row0 + 8;
            float c0 = acc[mb][n8][0], c1 = acc[mb][n8][1];
            float c2 = acc[mb][n8][2], c3 = acc[mb][n8][3];
            if (prior != 0.0f) {
                if (row0 == col) c0 += prior;
                if (row0 == col + 1) c1 += prior;
                if (row1 == col) c2 += prior;
                if (row1 == col + 1) c3 += prior;
            }
            *(float2*)&C[(size_t)row0 * ldc + col] = make_float2(c0, c1);
            *(float2*)&C[(size_t)row1 * ldc + col] = make_float2(c2, c3);
        }
    }
}

// ---------------- fp32 tile FMA core (Cholesky/solve GEMMs) ----------------
__device__ __forceinline__ void mm_tile_compute(const float (*As)[128], const float (*Bs)[128],
                                                float acc[8][8], int tr, int tc) {
#pragma unroll
    for (int kk = 0; kk < 16; kk++) {
        float ra[8], rb[8];
        *(float4*)&ra[0] = *(const float4*)&As[kk][tr * 8];
        *(float4*)&ra[4] = *(const float4*)&As[kk][tr * 8 + 4];
        *(float4*)&rb[0] = *(const float4*)&Bs[kk][tc * 8];
        *(float4*)&rb[4] = *(const float4*)&Bs[kk][tc * 8 + 4];
#pragma unroll
        for (int a = 0; a < 8; a++)
#pragma unroll
            for (int b = 0; b < 8; b++)
                acc[a][b] = fmaf(ra[a], rb[b], acc[a][b]);
    }
}

template <int TA, int TB>
__device__ __forceinline__ void gemm128(const float* __restrict__ A, int lda,
                                        const float* __restrict__ Bp, int ldb,
                                        float* __restrict__ C, int ldc,
                                        float alpha, int beta) {
    __shared__ float As[16][128];
    __shared__ float Bs[16][128];
    float acc[8][8];
#pragma unroll
    for (int a = 0; a < 8; a++)
#pragma unroll
        for (int b = 0; b < 8; b++) acc[a][b] = 0.0f;
    int tid = threadIdx.x;
    int tr = tid >> 4, tc = tid & 15;

    for (int k0 = 0; k0 < 128; k0 += 16) {
#pragma unroll
        for (int q = 0; q < 2; q++) {
            int idx = tid + q * 256;
            if (TA) {
                int kk = idx >> 5, m4 = (idx & 31) << 2;
                float4 v = *(const float4*)&A[(size_t)(k0 + kk) * lda + m4];
                *(float4*)&As[kk][m4] = v;
            } else {
                int rr = idx >> 2, c4 = (idx & 3) << 2;
                float4 v = *(const float4*)&A[(size_t)rr * lda + k0 + c4];
                As[c4 + 0][rr] = v.x; As[c4 + 1][rr] = v.y;
                As[c4 + 2][rr] = v.z; As[c4 + 3][rr] = v.w;
            }
            if (TB) {
                int rr = idx >> 2, c4 = (idx & 3) << 2;
                float4 v = *(const float4*)&Bp[(size_t)rr * ldb + k0 + c4];
                Bs[c4 + 0][rr] = v.x; Bs[c4 + 1][rr] = v.y;
                Bs[c4 + 2][rr] = v.z; Bs[c4 + 3][rr] = v.w;
            } else {
                int kk = idx >> 5, m4 = (idx & 31) << 2;
                float4 v = *(const float4*)&Bp[(size_t)(k0 + kk) * ldb + m4];
                *(float4*)&Bs[kk][m4] = v;
            }
        }
        __syncthreads();
        mm_tile_compute(As, Bs, acc, tr, tc);
        __syncthreads();
    }
#pragma unroll
    for (int a = 0; a < 8; a++) {
        int row = tr * 8 + a;
#pragma unroll
        for (int b = 0; b < 8; b++) {
            int col = tc * 8 + b;
            float v = alpha * acc[a][b];
            if (beta) v += C[(size_t)row * ldc + col];
            C[(size_t)row * ldc + col] = v;
        }
    }
}

// ---------------- Cholesky diag block: parallel factor + parallel inverse ----------------
// 512 threads: 4 threads per row (factor) / 4 threads per column (inverse).
__global__ __launch_bounds__(512) void potf2_kernel(int kb) {
    extern __shared__ float sh[];
    float (*Ls)[129] = (float(*)[129])sh;
    float (*Iv)[129] = (float(*)[129])(sh + 128 * 129);
    __shared__ float red[128];
    __shared__ float rdg[128];
    int s = blockIdx.x;
    int tid = threadIdx.x;
    int r = tid >> 2;        // row (factor) / column (inverse)
    int q = tid & 3;
    float* Ablk = g_prec + (size_t)s * DDIM * DDIM + (size_t)kb * 128 * DDIM + kb * 128;

    for (int idx = tid; idx < 128 * 128; idx += 512)
        Ls[idx >> 7][idx & 127] = Ablk[(size_t)(idx >> 7) * DDIM + (idx & 127)];
    __syncthreads();

    // factor: 2 syncs per column, rank-1 update parallelized 4-wide per row
    for (int j = 0; j < 128; j++) {
        float d = Ls[j][j];
        float inv = 1.0f / sqrtf(d);
        if (q == 0 && r > j) Ls[r][j] *= inv;
        __syncthreads();
        if (r > j) {
            float lrj = Ls[r][j];
            for (int c = j + 1 + q; c <= r; c += 4)
                Ls[r][c] -= lrj * Ls[c][j];
        } else if (r == j && q == 0) {
            Ls[j][j] = d * inv;   // sqrt(d); no reader of [j][j] in this phase
        }
        __syncthreads();
    }

    // diag reciprocals + logdet partials
    if (tid < 128) {
        rdg[tid] = 1.0f / Ls[tid][tid];
        red[tid] = 2.0f * logf(Ls[tid][tid]);
    }
    __syncthreads();
    for (int off = 64; off; off >>= 1) {
        if (tid < off) red[tid] += red[tid + off];
        __syncthreads();
    }
    if (tid == 0) g_logdet_part[s * NBLK + kb] = red[0];

    // write back factored block
    for (int idx = tid; idx < 128 * 128; idx += 512)
        Ablk[(size_t)(idx >> 7) * DDIM + (idx & 127)] = Ls[idx >> 7][idx & 127];

    // inverse: 4 threads per column, forward substitution, shfl butterfly per row
    int col = r;
    for (int i = 0; i < 128; i++) {
        float part = 0.0f;
        if (i > col) {
            for (int t = col + q; t < i; t += 4)
                part -= Ls[i][t] * Iv[t][col];
        }
        part += __shfl_xor_sync(0xffffffffu, part, 1);
        part += __shfl_xor_sync(0xffffffffu, part, 2);
        if (q == 0) {
            float v;
            if (i == col)      v = rdg[i];
            else if (i > col)  v = part * rdg[i];
            else               v = 0.0f;
            Iv[i][col] = v;
        }
        __syncwarp();
    }
    __syncthreads();
    float* Dst = g_Dinv + ((size_t)s * NBLK + kb) * 128 * 128;
    for (int idx = tid; idx < 128 * 128; idx += 512)
        Dst[idx] = Iv[idx >> 7][idx & 127];
}

__global__ __launch_bounds__(256) void chol_trsm_kernel(int k) {
    int s = blockIdx.z;
    int i = k + 1 + blockIdx.x;
    float* Ablk = g_prec + (size_t)s * DDIM * DDIM + (size_t)i * 128 * DDIM + k * 128;
    const float* Dinv = g_Dinv + ((size_t)s * NBLK + k) * 128 * 128;
    gemm128<0, 1>(Ablk, DDIM, Dinv, 128, Ablk, DDIM, 1.0f, 0);
}

__global__ __launch_bounds__(256) void chol_syrk_kernel(int k) {
    int s = blockIdx.z;
    int t = blockIdx.x;
    int a = 0;
    while ((a + 1) * (a + 2) / 2 <= t) a++;
    int b = t - a * (a + 1) / 2;
    int i = k + 1 + a, j = k + 1 + b;
    const float* Aik = g_prec + (size_t)s * DDIM * DDIM + (size_t)i * 128 * DDIM + k * 128;
    const float* Ajk = g_prec + (size_t)s * DDIM * DDIM + (size_t)j * 128 * DDIM + k * 128;
    float* Cij = g_prec + (size_t)s * DDIM * DDIM + (size_t)i * 128 * DDIM + j * 128;
    gemm128<0, 1>(Aik, DDIM, Ajk, DDIM, Cij, DDIM, -1.0f, 1);
}

// ---------------- triangular solves ----------------
__global__ __launch_bounds__(256) void fsolve_diag_kernel(int k) {
    int s = blockIdx.z;
    int ct = blockIdx.x;
    float* Rk = g_R + (size_t)s * DDIM * NCOUT + (size_t)k * 128 * NCOUT + ct * 128;
    const float* Dinv = g_Dinv + ((size_t)s * NBLK + k) * 128 * 128;
    gemm128<0, 0>(Dinv, 128, Rk, NCOUT, Rk, NCOUT, 1.0f, 0);
}

__global__ __launch_bounds__(256) void fsolve_update_kernel(int k) {
    int s = blockIdx.z;
    int ct = blockIdx.x;
    int i = k + 1 + blockIdx.y;
    const float* A = g_prec + (size_t)s * DDIM * DDIM + (size_t)i * 128 * DDIM + k * 128;
    const float* Rk = g_R + (size_t)s * DDIM * NCOUT + (size_t)k * 128 * NCOUT + ct * 128;
    float* Ri = g_R + (size_t)s * DDIM * NCOUT + (size_t)i * 128 * NCOUT + ct * 128;
    gemm128<0, 0>(A, DDIM, Rk, NCOUT, Ri, NCOUT, -1.0f, 1);
}

__global__ __launch_bounds__(256) void addz_kernel(const float* __restrict__ Z) {
    size_t i = (size_t)blockIdx.x * 256 + threadIdx.x;
    int c = (int)(i % NCOUT);
    size_t r = i / NCOUT;
    int d = (int)(r % DDIM);
    int s = (int)(r / DDIM);
    g_R[i] += Z[((size_t)s * NCOUT + c) * DDIM + d];
}

__global__ __launch_bounds__(256) void bsolve_diag_kernel(int k) {
    int s = blockIdx.z;
    int ct = blockIdx.x;
    float* Rk = g_R + (size_t)s * DDIM * NCOUT + (size_t)k * 128 * NCOUT + ct * 128;
    const float* Dinv = g_Dinv + ((size_t)s * NBLK + k) * 128 * 128;
    gemm128<1, 0>(Dinv, 128, Rk, NCOUT, Rk, NCOUT, 1.0f, 0);
}

__global__ __launch_bounds__(256) void bsolve_update_kernel(int k) {
    int s = blockIdx.z;
    int ct = blockIdx.x;
    int i = blockIdx.y;
    const float* A = g_prec + (size_t)s * DDIM * DDIM + (size_t)k * 128 * DDIM + i * 128;
    const float* Rk = g_R + (size_t)s * DDIM * NCOUT + (size_t)k * 128 * NCOUT + ct * 128;
    float* Ri = g_R + (size_t)s * DDIM * NCOUT + (size_t)i * 128 * NCOUT + ct * 128;
    gemm128<1, 0>(A, DDIM, Rk, NCOUT, Ri, NCOUT, -1.0f, 1);
}

// ---------------- output + reductions ----------------
__global__ __launch_bounds__(256) void finalize_kernel(const float* __restrict__ Z,
                                                       float* __restrict__ outW) {
    __shared__ float red[256];
    size_t i = (size_t)blockIdx.x * 256 + threadIdx.x;
    int d = (int)(i % DDIM);
    size_t r = i / DDIM;
    int c = (int)(r % NCOUT);
    int s = (int)(r / NCOUT);
    float w = g_R[((size_t)s * DDIM + d) * NCOUT + c];
    outW[i] = w;
    float z = Z[i];
    red[threadIdx.x] = 0.5f * z * z - 0.5f * w * w;
    __syncthreads();
    for (int off = 128; off; off >>= 1) {
        if (threadIdx.x < off) red[threadIdx.x] += red[threadIdx.x + off];
        __syncthreads();
    }
    if (threadIdx.x == 0) g_part[blockIdx.x] = red[0];
}

__global__ __launch_bounds__(256) void logpq_kernel(float* __restrict__ outL) {
    __shared__ float red[256];
    int s = blockIdx.x;
    float acc = 0.0f;
    for (int i = threadIdx.x; i < 1152; i += 256) acc += g_part[s * 1152 + i];
    red[threadIdx.x] = acc;
    __syncthreads();
    for (int off = 128; off; off >>= 1) {
        if (threadIdx.x < off) red[threadIdx.x] += red[threadIdx.x + off];
        __syncthreads();
    }
    if (threadIdx.x == 0) {
        float ld = 0.0f;
        for (int k = 0; k < NBLK; k++) ld += g_logdet_part[s * NBLK + k];
        outL[s] = red[0] - 0.5f * (float)NCOUT * ld;
    }
}

// ---------------- launch ----------------
extern "C" void kernel_launch(void* const* d_in, const int* in_sizes, int n_in,
                              void* d_out, int out_size) {
    const float* X  = (const float*)d_in[0];
    const float* u  = (const float*)d_in[1];
    const float* lp = (const float*)d_in[2];
    const float* Z  = (const float*)d_in[3];
    float* outW = (float*)d_out;
    float* outL = outW + (size_t)NS * NCOUT * DDIM;

    cudaFuncSetAttribute(potf2_kernel, cudaFuncAttributeMaxDynamicSharedMemorySize, 135168);
    cudaFuncSetAttribute(tc_gram_kernel, cudaFuncAttributeMaxDynamicSharedMemorySize, GRAM_SMEM);

    build_patches<<<147456, 256>>>(X, lp);
    build_yt<<<8192, 256>>>(u, lp);
    tc_gram_kernel<<<dim3(63, NS), 256, GRAM_SMEM>>>();

    for (int k = 0; k < NBLK; k++) {
        potf2_kernel<<<NS, 512, 2 * 128 * 129 * sizeof(float)>>>(k);
        int rem = NBLK - 1 - k;
        if (rem > 0) {
            chol_trsm_kernel<<<dim3(rem, 1, NS), 256>>>(k);
            chol_syrk_kernel<<<dim3(rem * (rem + 1) / 2, 1, NS), 256>>>(k);
        }
    }

    for (int k = 0; k < NBLK; k++) {
        fsolve_diag_kernel<<<dim3(2, 1, NS), 256>>>(k);
        if (k < NBLK - 1) fsolve_update_kernel<<<dim3(2, NBLK - 1 - k, NS), 256>>>(k);
    }
    addz_kernel<<<4608, 256>>>(Z);
    for (int k = NBLK - 1; k >= 0; k--) {
        bsolve_diag_kernel<<<dim3(2, 1, NS), 256>>>(k);
        if (k > 0) bsolve_update_kernel<<<dim3(2, k, NS), 256>>>(k);
    }

    finalize_kernel<<<4608, 256>>>(Z, outW);
    logpq_kernel<<<NS, 256>>>(outL);
}

// round 6
// speedup vs baseline: 3.1934x; 1.0452x over previous
#include <cuda_runtime.h>
#include <cuda_bf16.h>
#include <math.h>
#include <stdint.h>

// ---------------- problem constants ----------------
#define NS     4
#define NBATCH 32
#define NCIN   128
#define NCOUT  256
#define HH     16
#define WW     16
#define DDIM   1152
#define NPIX   256
#define NCOLS  8192
#define NBLK   9

// ---------------- scratch ----------------
__device__ __nv_bfloat16 g_Phi[(size_t)NS * DDIM * NCOLS];
__device__ __nv_bfloat16 g_Plo[(size_t)NS * DDIM * NCOLS];
__device__ __nv_bfloat16 g_Yhi[(size_t)NCOUT * NCOLS];
__device__ __nv_bfloat16 g_Ylo[(size_t)NCOUT * NCOLS];
__device__ float g_prec[(size_t)NS * DDIM * DDIM];
__device__ float g_R   [(size_t)NS * DDIM * NCOUT];
__device__ float g_Dinv[(size_t)NS * NBLK * 128 * 128];
__device__ float g_logdet_part[NS * NBLK];
__device__ float g_part[NS * 1152];

// ---------------- helpers ----------------
__device__ __forceinline__ uint32_t smem_u32(const void* p) {
    uint32_t a;
    asm("{ .reg .u64 t; cvta.to.shared.u64 t, %1; cvt.u32.u64 %0, t; }" : "=r"(a) : "l"(p));
    return a;
}

#define CP_ASYNC16(dst, src) \
    asm volatile("cp.async.cg.shared.global [%0], [%1], 16;" :: "r"(dst), "l"(src) : "memory")
#define CP_COMMIT() asm volatile("cp.async.commit_group;" ::: "memory")
#define CP_WAIT1()  asm volatile("cp.async.wait_group 1;" ::: "memory")

#define LDMATRIX_X4(r0, r1, r2, r3, addr) \
    asm volatile("ldmatrix.sync.aligned.m8n8.x4.shared.b16 {%0,%1,%2,%3}, [%4];" \
        : "=r"(r0), "=r"(r1), "=r"(r2), "=r"(r3) : "r"(addr))

#define MMA16816(d, a, b0, b1) \
    asm volatile("mma.sync.aligned.m16n8k16.row.col.f32.bf16.bf16.f32 " \
        "{%0,%1,%2,%3}, {%4,%5,%6,%7}, {%8,%9}, {%0,%1,%2,%3};" \
        : "+f"((d)[0]), "+f"((d)[1]), "+f"((d)[2]), "+f"((d)[3]) \
        : "r"((a)[0]), "r"((a)[1]), "r"((a)[2]), "r"((a)[3]), "r"(b0), "r"(b1))

__device__ __forceinline__ uint32_t sw128(uint32_t off) {
    return off ^ ((off >> 3) & 0x70);
}

// ---------------- patch build (bf16 hi/lo) ----------------
__global__ __launch_bounds__(256) void build_patches(const float* __restrict__ X,
                                                     const float* __restrict__ lp) {
    size_t i = (size_t)blockIdx.x * 256 + threadIdx.x;
    int n = (int)(i % NCOLS);
    size_t r = i / NCOLS;
    int d = (int)(r % DDIM);
    int s = (int)(r / DDIM);
    int b = n >> 8;
    int p = n & 255;
    int y = p >> 4, x = p & 15;
    int cin = d / 9;
    int rem = d - cin * 9;
    int kh = rem / 3, kw = rem - kh * 3;
    int yy = y + kh - 1, xx = x + kw - 1;
    float v = 0.0f;
    if (yy >= 0 && yy < HH && xx >= 0 && xx < WW) {
        float sp = expf(0.5f * lp[b]);
        v = sp * X[((((size_t)s * NBATCH + b) * NCIN + cin) * HH + yy) * WW + xx];
    }
    __nv_bfloat16 hi = __float2bfloat16_rn(v);
    g_Phi[i] = hi;
    g_Plo[i] = __float2bfloat16_rn(v - __bfloat162float(hi));
}

__global__ __launch_bounds__(256) void build_yt(const float* __restrict__ u,
                                                const float* __restrict__ lp) {
    size_t i = (size_t)blockIdx.x * 256 + threadIdx.x;
    int n = (int)(i % NCOLS);
    int c = (int)(i / NCOLS);
    int b = n >> 8;
    int p = n & 255;
    float v = expf(0.5f * lp[b]) * u[((size_t)b * NCOUT + c) * NPIX + p];
    __nv_bfloat16 hi = __float2bfloat16_rn(v);
    g_Yhi[i] = hi;
    g_Ylo[i] = __float2bfloat16_rn(v - __bfloat162float(hi));
}

// ---------------- warp-MMA Gram kernel (XLX lower tiles + XLY) ----------------
#define TILE_B 16384
#define BUF_B  65536
#define GRAM_SMEM (2 * BUF_B)

__global__ __launch_bounds__(256, 1) void tc_gram_kernel() {
    extern __shared__ char sm[];
    uint32_t smb = smem_u32(sm);
    int tid = threadIdx.x;
    int wid = tid >> 5, lid = tid & 31;
    int s = blockIdx.y;
    int t = blockIdx.x;

    const __nv_bfloat16 *Ah, *Al, *Bh, *Bl;
    float* C;
    int ldc;
    float prior;
    if (t < 45) {
        int bi = 0;
        while ((bi + 1) * (bi + 2) / 2 <= t) bi++;
        int bj = t - bi * (bi + 1) / 2;
        size_t ar = (size_t)(s * DDIM + bi * 128) * NCOLS;
        size_t br = (size_t)(s * DDIM + bj * 128) * NCOLS;
        Ah = g_Phi + ar; Al = g_Plo + ar;
        Bh = g_Phi + br; Bl = g_Plo + br;
        C = g_prec + (size_t)s * DDIM * DDIM + (size_t)bi * 128 * DDIM + bj * 128;
        ldc = DDIM;
        prior = (bi == bj) ? 1.0f : 0.0f;
    } else {
        int u2 = t - 45;
        int bi = u2 >> 1, bj = u2 & 1;
        size_t ar = (size_t)(s * DDIM + bi * 128) * NCOLS;
        size_t br = (size_t)bj * 128 * NCOLS;
        Ah = g_Phi + ar; Al = g_Plo + ar;
        Bh = g_Yhi + br; Bl = g_Ylo + br;
        C = g_R + (size_t)s * DDIM * NCOUT + (size_t)bi * 128 * NCOUT + bj * 128;
        ldc = NCOUT;
        prior = 0.0f;
    }

    int lrow[4], lseg[4];
    uint32_t lsw[4];
#pragma unroll
    for (int j = 0; j < 4; j++) {
        int idx = tid + j * 256;
        lrow[j] = idx >> 3;
        lseg[j] = idx & 7;
        lsw[j] = sw128((uint32_t)(lrow[j] * 128 + lseg[j] * 16));
    }

    float acc[2][8][4];
#pragma unroll
    for (int a = 0; a < 2; a++)
#pragma unroll
        for (int b = 0; b < 8; b++)
#pragma unroll
            for (int c = 0; c < 4; c++) acc[a][b][c] = 0.0f;

    int wm = (wid >> 1) * 32;
    int wn = (wid & 1) * 64;
    int l16 = lid & 15;
    int kseg16 = (lid >> 4) * 16;

    {
#pragma unroll
        for (int arr = 0; arr < 4; arr++) {
            const __nv_bfloat16* G = (arr == 0) ? Ah : (arr == 1) ? Al : (arr == 2) ? Bh : Bl;
#pragma unroll
            for (int j = 0; j < 4; j++)
                CP_ASYNC16(smb + arr * TILE_B + lsw[j],
                           G + (size_t)lrow[j] * NCOLS + lseg[j] * 8);
        }
        CP_COMMIT();
    }

    for (int i = 0; i < 128; i++) {
        int buf = i & 1;
        if (i + 1 < 128) {
            int k0 = (i + 1) * 64;
            uint32_t bb = smb + ((i + 1) & 1) * BUF_B;
#pragma unroll
            for (int arr = 0; arr < 4; arr++) {
                const __nv_bfloat16* G = (arr == 0) ? Ah : (arr == 1) ? Al : (arr == 2) ? Bh : Bl;
#pragma unroll
                for (int j = 0; j < 4; j++)
                    CP_ASYNC16(bb + arr * TILE_B + lsw[j],
                               G + (size_t)lrow[j] * NCOLS + k0 + lseg[j] * 8);
            }
        }
        CP_COMMIT();
        CP_WAIT1();
        __syncthreads();

        uint32_t base = smb + buf * BUF_B;
#pragma unroll
        for (int ks = 0; ks < 4; ks++) {
            int kb = ks * 32 + kseg16;
            uint32_t ah[2][4], al[2][4], bh[4][4], bl[4][4];
#pragma unroll
            for (int mb = 0; mb < 2; mb++) {
                uint32_t off = sw128((uint32_t)((wm + mb * 16 + l16) * 128 + kb));
                LDMATRIX_X4(ah[mb][0], ah[mb][1], ah[mb][2], ah[mb][3], base + off);
                LDMATRIX_X4(al[mb][0], al[mb][1], al[mb][2], al[mb][3], base + TILE_B + off);
            }
#pragma unroll
            for (int nb = 0; nb < 4; nb++) {
                uint32_t off = sw128((uint32_t)((wn + nb * 16 + l16) * 128 + kb));
                LDMATRIX_X4(bh[nb][0], bh[nb][1], bh[nb][2], bh[nb][3], base + 2 * TILE_B + off);
                LDMATRIX_X4(bl[nb][0], bl[nb][1], bl[nb][2], bl[nb][3], base + 3 * TILE_B + off);
            }
#pragma unroll
            for (int mb = 0; mb < 2; mb++)
#pragma unroll
                for (int n8 = 0; n8 < 8; n8++) {
                    int nb = n8 >> 1, h = n8 & 1;
                    MMA16816(acc[mb][n8], ah[mb], bh[nb][h], bh[nb][h + 2]);
                    MMA16816(acc[mb][n8], ah[mb], bl[nb][h], bl[nb][h + 2]);
                    MMA16816(acc[mb][n8], al[mb], bh[nb][h], bh[nb][h + 2]);
                }
        }
        __syncthreads();
    }

    int tq = lid >> 2;
    int tc2 = (lid & 3) * 2;
#pragma unroll
    for (int mb = 0; mb < 2; mb++) {
#pragma unroll
        for (int n8 = 0; n8 < 8; n8++) {
            int col = wn + n8 * 8 + tc2;
            int row0 = wm + mb * 16 + tq;
            int row1 = row0 + 8;
            float c0 = acc[mb][n8][0], c1 = acc[mb][n8][1];
            float c2 = acc[mb][n8][2], c3 = acc[mb][n8][3];
            if (prior != 0.0f) {
                if (row0 == col) c0 += prior;
                if (row0 == col + 1) c1 += prior;
                if (row1 == col) c2 += prior;
                if (row1 == col + 1) c3 += prior;
            }
            *(float2*)&C[(size_t)row0 * ldc + col] = make_float2(c0, c1);
            *(float2*)&C[(size_t)row1 * ldc + col] = make_float2(c2, c3);
        }
    }
}

// ---------------- fp32 tile FMA core (Cholesky/solve GEMMs) ----------------
__device__ __forceinline__ void mm_tile_compute(const float (*As)[128], const float (*Bs)[128],
                                                float acc[8][8], int tr, int tc) {
#pragma unroll
    for (int kk = 0; kk < 16; kk++) {
        float ra[8], rb[8];
        *(float4*)&ra[0] = *(const float4*)&As[kk][tr * 8];
        *(float4*)&ra[4] = *(const float4*)&As[kk][tr * 8 + 4];
        *(float4*)&rb[0] = *(const float4*)&Bs[kk][tc * 8];
        *(float4*)&rb[4] = *(const float4*)&Bs[kk][tc * 8 + 4];
#pragma unroll
        for (int a = 0; a < 8; a++)
#pragma unroll
            for (int b = 0; b < 8; b++)
                acc[a][b] = fmaf(ra[a], rb[b], acc[a][b]);
    }
}

template <int TA, int TB>
__device__ __forceinline__ void gemm128(const float* __restrict__ A, int lda,
                                        const float* __restrict__ Bp, int ldb,
                                        float* __restrict__ C, int ldc,
                                        float alpha, int beta) {
    __shared__ float As[16][128];
    __shared__ float Bs[16][128];
    float acc[8][8];
#pragma unroll
    for (int a = 0; a < 8; a++)
#pragma unroll
        for (int b = 0; b < 8; b++) acc[a][b] = 0.0f;
    int tid = threadIdx.x;
    int tr = tid >> 4, tc = tid & 15;

    for (int k0 = 0; k0 < 128; k0 += 16) {
#pragma unroll
        for (int q = 0; q < 2; q++) {
            int idx = tid + q * 256;
            if (TA) {
                int kk = idx >> 5, m4 = (idx & 31) << 2;
                float4 v = *(const float4*)&A[(size_t)(k0 + kk) * lda + m4];
                *(float4*)&As[kk][m4] = v;
            } else {
                int rr = idx >> 2, c4 = (idx & 3) << 2;
                float4 v = *(const float4*)&A[(size_t)rr * lda + k0 + c4];
                As[c4 + 0][rr] = v.x; As[c4 + 1][rr] = v.y;
                As[c4 + 2][rr] = v.z; As[c4 + 3][rr] = v.w;
            }
            if (TB) {
                int rr = idx >> 2, c4 = (idx & 3) << 2;
                float4 v = *(const float4*)&Bp[(size_t)rr * ldb + k0 + c4];
                Bs[c4 + 0][rr] = v.x; Bs[c4 + 1][rr] = v.y;
                Bs[c4 + 2][rr] = v.z; Bs[c4 + 3][rr] = v.w;
            } else {
                int kk = idx >> 5, m4 = (idx & 31) << 2;
                float4 v = *(const float4*)&Bp[(size_t)(k0 + kk) * ldb + m4];
                *(float4*)&Bs[kk][m4] = v;
            }
        }
        __syncthreads();
        mm_tile_compute(As, Bs, acc, tr, tc);
        __syncthreads();
    }
#pragma unroll
    for (int a = 0; a < 8; a++) {
        int row = tr * 8 + a;
#pragma unroll
        for (int b = 0; b < 8; b++) {
            int col = tc * 8 + b;
            float v = alpha * acc[a][b];
            if (beta) v += C[(size_t)row * ldc + col];
            C[(size_t)row * ldc + col] = v;
        }
    }
}

// ---------------- Cholesky diag block: 32-blocked factor + blocked inverse ----------------
// SMEM layout (dynamic): Ls[128][129] | Iv[128][129] | Tbuf[3][32][33]
__global__ __launch_bounds__(512) void potf2_kernel(int kb) {
    extern __shared__ float sh[];
    float (*Ls)[129] = (float(*)[129])sh;
    float (*Iv)[129] = (float(*)[129])(sh + 128 * 129);
    float (*Tbuf)[33] = (float(*)[33])(sh + 2 * 128 * 129);  // [3*32][33]
    __shared__ float red[128];
    int s = blockIdx.x;
    int tid = threadIdx.x;
    float* Ablk = g_prec + (size_t)s * DDIM * DDIM + (size_t)kb * 128 * DDIM + kb * 128;

    // load block; zero Iv
    for (int idx = tid; idx < 128 * 128; idx += 512)
        Ls[idx >> 7][idx & 127] = Ablk[(size_t)(idx >> 7) * DDIM + (idx & 127)];
    for (int idx = tid; idx < 128 * 129; idx += 512)
        ((float*)Iv)[idx] = 0.0f;
    __syncthreads();

    for (int p = 0; p < 4; p++) {
        int c0 = p * 32;
        // (a) 32x32 diag factor — warp 0, lane = row
        if (tid < 32) {
            int r = tid;
#pragma unroll 1
            for (int j = 0; j < 32; j++) {
                float d = Ls[c0 + j][c0 + j];
                __syncwarp();
                float inv = 1.0f / sqrtf(d);
                if (r == j) Ls[c0 + j][c0 + j] = d * inv;
                else if (r > j) Ls[c0 + r][c0 + j] *= inv;
                __syncwarp();
                if (r > j) {
                    float lrj = Ls[c0 + r][c0 + j];
                    for (int c = j + 1; c <= r; c++)
                        Ls[c0 + r][c0 + c] -= lrj * Ls[c0 + c][c0 + j];
                }
                __syncwarp();
            }
        }
        __syncthreads();
        // (b) 32x32 triangular inverse — warp 0, lane = column
        if (tid < 32) {
            int c = tid;
#pragma unroll 1
            for (int i = 0; i < 32; i++) {
                float v;
                if (i < c) v = 0.0f;
                else if (i == c) v = 1.0f / Ls[c0 + i][c0 + i];
                else {
                    float sum = 0.0f;
                    for (int t = c; t < i; t++)
                        sum += Ls[c0 + i][c0 + t] * Iv[c0 + t][c0 + c];
                    v = -sum / Ls[c0 + i][c0 + i];
                }
                Iv[c0 + i][c0 + c] = v;
                __syncwarp();
            }
        }
        __syncthreads();

        if (p < 3) {
            int base = c0 + 32;
            int nrows = 128 - base;
            int nout = nrows * 32;
            // (c) TRSM: panel = panel @ inv(Ldd)^T, register-staged in-place
            float vreg[6];
            int cnt = 0;
            for (int e = tid; e < nout; e += 512, cnt++) {
                int ri = base + (e >> 5);
                int c = e & 31;
                float acc = 0.0f;
#pragma unroll
                for (int t = 0; t < 32; t++)
                    acc += Ls[ri][c0 + t] * Iv[c0 + c][c0 + t];
                vreg[cnt] = acc;
            }
            __syncthreads();
            cnt = 0;
            for (int e = tid; e < nout; e += 512, cnt++)
                Ls[base + (e >> 5)][c0 + (e & 31)] = vreg[cnt];
            __syncthreads();
            // (d) SYRK trailing (full square, symmetric), 4x4 register tiles
            int tpr = nrows >> 2;
            int ntile = tpr * tpr;
            for (int e = tid; e < ntile; e += 512) {
                int ti = e / tpr, tj = e - ti * tpr;
                int r0 = base + ti * 4, q0 = base + tj * 4;
                float accq[4][4];
#pragma unroll
                for (int a = 0; a < 4; a++)
#pragma unroll
                    for (int b = 0; b < 4; b++)
                        accq[a][b] = Ls[r0 + a][q0 + b];
#pragma unroll
                for (int t = 0; t < 32; t++) {
                    float av[4], bv[4];
#pragma unroll
                    for (int a = 0; a < 4; a++) av[a] = Ls[r0 + a][c0 + t];
#pragma unroll
                    for (int b = 0; b < 4; b++) bv[b] = Ls[q0 + b][c0 + t];
#pragma unroll
                    for (int a = 0; a < 4; a++)
#pragma unroll
                        for (int b = 0; b < 4; b++)
                            accq[a][b] -= av[a] * bv[b];
                }
#pragma unroll
                for (int a = 0; a < 4; a++)
#pragma unroll
                    for (int b = 0; b < 4; b++)
                        Ls[r0 + a][q0 + b] = accq[a][b];
            }
            __syncthreads();
        }
    }

    // logdet partials
    if (tid < 128) red[tid] = 2.0f * logf(Ls[tid][tid]);
    __syncthreads();
    for (int off = 64; off; off >>= 1) {
        if (tid < off) red[tid] += red[tid + off];
        __syncthreads();
    }
    if (tid == 0) g_logdet_part[s * NBLK + kb] = red[0];

    // compose full 128x128 inverse: M_ij = -Dinv_ii @ (sum_t L_it M_tj)
    int grp = tid >> 7;       // 0..3  (block column j = grp)
    int gt = tid & 127;
    int tr = gt >> 4;         // 0..7 -> rows tr*4..tr*4+3
    int tcg = gt & 15;        // cols tcg*2, tcg*2+1
    for (int step = 1; step <= 3; step++) {
        int j = grp, i = grp + step;
        bool act = (i <= 3);
        if (act) {
            float acc[4][2];
#pragma unroll
            for (int a = 0; a < 4; a++) { acc[a][0] = 0.0f; acc[a][1] = 0.0f; }
            for (int t = j; t < i; t++) {
#pragma unroll 1
                for (int u = 0; u < 32; u++) {
                    float b0 = Iv[32 * t + u][32 * j + tcg * 2];
                    float b1 = Iv[32 * t + u][32 * j + tcg * 2 + 1];
#pragma unroll
                    for (int a = 0; a < 4; a++) {
                        float av = Ls[32 * i + tr * 4 + a][32 * t + u];
                        acc[a][0] += av * b0;
                        acc[a][1] += av * b1;
                    }
                }
            }
#pragma unroll
            for (int a = 0; a < 4; a++) {
                Tbuf[grp * 32 + tr * 4 + a][tcg * 2]     = acc[a][0];
                Tbuf[grp * 32 + tr * 4 + a][tcg * 2 + 1] = acc[a][1];
            }
        }
        __syncthreads();
        if (act) {
            float acc[4][2];
#pragma unroll
            for (int a = 0; a < 4; a++) { acc[a][0] = 0.0f; acc[a][1] = 0.0f; }
#pragma unroll 1
            for (int u = 0; u < 32; u++) {
                float b0 = Tbuf[grp * 32 + u][tcg * 2];
                float b1 = Tbuf[grp * 32 + u][tcg * 2 + 1];
#pragma unroll
                for (int a = 0; a < 4; a++) {
                    float av = Iv[32 * i + tr * 4 + a][32 * i + u];
                    acc[a][0] += av * b0;
                    acc[a][1] += av * b1;
                }
            }
#pragma unroll
            for (int a = 0; a < 4; a++) {
                Iv[32 * i + tr * 4 + a][32 * j + tcg * 2]     = -acc[a][0];
                Iv[32 * i + tr * 4 + a][32 * j + tcg * 2 + 1] = -acc[a][1];
            }
        }
        __syncthreads();
    }

    // write Dinv
    float* Dst = g_Dinv + ((size_t)s * NBLK + kb) * 128 * 128;
    for (int idx = tid; idx < 128 * 128; idx += 512)
        Dst[idx] = Iv[idx >> 7][idx & 127];
}

__global__ __launch_bounds__(256) void chol_trsm_kernel(int k) {
    int s = blockIdx.z;
    int i = k + 1 + blockIdx.x;
    float* Ablk = g_prec + (size_t)s * DDIM * DDIM + (size_t)i * 128 * DDIM + k * 128;
    const float* Dinv = g_Dinv + ((size_t)s * NBLK + k) * 128 * 128;
    gemm128<0, 1>(Ablk, DDIM, Dinv, 128, Ablk, DDIM, 1.0f, 0);
}

__global__ __launch_bounds__(256) void chol_syrk_kernel(int k) {
    int s = blockIdx.z;
    int t = blockIdx.x;
    int a = 0;
    while ((a + 1) * (a + 2) / 2 <= t) a++;
    int b = t - a * (a + 1) / 2;
    int i = k + 1 + a, j = k + 1 + b;
    const float* Aik = g_prec + (size_t)s * DDIM * DDIM + (size_t)i * 128 * DDIM + k * 128;
    const float* Ajk = g_prec + (size_t)s * DDIM * DDIM + (size_t)j * 128 * DDIM + k * 128;
    float* Cij = g_prec + (size_t)s * DDIM * DDIM + (size_t)i * 128 * DDIM + j * 128;
    gemm128<0, 1>(Aik, DDIM, Ajk, DDIM, Cij, DDIM, -1.0f, 1);
}

// ---------------- triangular solves ----------------
__global__ __launch_bounds__(256) void fsolve_diag_kernel(int k) {
    int s = blockIdx.z;
    int ct = blockIdx.x;
    float* Rk = g_R + (size_t)s * DDIM * NCOUT + (size_t)k * 128 * NCOUT + ct * 128;
    const float* Dinv = g_Dinv + ((size_t)s * NBLK + k) * 128 * 128;
    gemm128<0, 0>(Dinv, 128, Rk, NCOUT, Rk, NCOUT, 1.0f, 0);
}

__global__ __launch_bounds__(256) void fsolve_update_kernel(int k) {
    int s = blockIdx.z;
    int ct = blockIdx.x;
    int i = k + 1 + blockIdx.y;
    const float* A = g_prec + (size_t)s * DDIM * DDIM + (size_t)i * 128 * DDIM + k * 128;
    const float* Rk = g_R + (size_t)s * DDIM * NCOUT + (size_t)k * 128 * NCOUT + ct * 128;
    float* Ri = g_R + (size_t)s * DDIM * NCOUT + (size_t)i * 128 * NCOUT + ct * 128;
    gemm128<0, 0>(A, DDIM, Rk, NCOUT, Ri, NCOUT, -1.0f, 1);
}

__global__ __launch_bounds__(256) void addz_kernel(const float* __restrict__ Z) {
    size_t i = (size_t)blockIdx.x * 256 + threadIdx.x;
    int c = (int)(i % NCOUT);
    size_t r = i / NCOUT;
    int d = (int)(r % DDIM);
    int s = (int)(r / DDIM);
    g_R[i] += Z[((size_t)s * NCOUT + c) * DDIM + d];
}

__global__ __launch_bounds__(256) void bsolve_diag_kernel(int k) {
    int s = blockIdx.z;
    int ct = blockIdx.x;
    float* Rk = g_R + (size_t)s * DDIM * NCOUT + (size_t)k * 128 * NCOUT + ct * 128;
    const float* Dinv = g_Dinv + ((size_t)s * NBLK + k) * 128 * 128;
    gemm128<1, 0>(Dinv, 128, Rk, NCOUT, Rk, NCOUT, 1.0f, 0);
}

__global__ __launch_bounds__(256) void bsolve_update_kernel(int k) {
    int s = blockIdx.z;
    int ct = blockIdx.x;
    int i = blockIdx.y;
    const float* A = g_prec + (size_t)s * DDIM * DDIM + (size_t)k * 128 * DDIM + i * 128;
    const float* Rk = g_R + (size_t)s * DDIM * NCOUT + (size_t)k * 128 * NCOUT + ct * 128;
    float* Ri = g_R + (size_t)s * DDIM * NCOUT + (size_t)i * 128 * NCOUT + ct * 128;
    gemm128<1, 0>(A, DDIM, Rk, NCOUT, Ri, NCOUT, -1.0f, 1);
}

// ---------------- output + reductions ----------------
__global__ __launch_bounds__(256) void finalize_kernel(const float* __restrict__ Z,
                                                       float* __restrict__ outW) {
    __shared__ float red[256];
    size_t i = (size_t)blockIdx.x * 256 + threadIdx.x;
    int d = (int)(i % DDIM);
    size_t r = i / DDIM;
    int c = (int)(r % NCOUT);
    int s = (int)(r / NCOUT);
    float w = g_R[((size_t)s * DDIM + d) * NCOUT + c];
    outW[i] = w;
    float z = Z[i];
    red[threadIdx.x] = 0.5f * z * z - 0.5f * w * w;
    __syncthreads();
    for (int off = 128; off; off >>= 1) {
        if (threadIdx.x < off) red[threadIdx.x] += red[threadIdx.x + off];
        __syncthreads();
    }
    if (threadIdx.x == 0) g_part[blockIdx.x] = red[0];
}

__global__ __launch_bounds__(256) void logpq_kernel(float* __restrict__ outL) {
    __shared__ float red[256];
    int s = blockIdx.x;
    float acc = 0.0f;
    for (int i = threadIdx.x; i < 1152; i += 256) acc += g_part[s * 1152 + i];
    red[threadIdx.x] = acc;
    __syncthreads();
    for (int off = 128; off; off >>= 1) {
        if (threadIdx.x < off) red[threadIdx.x] += red[threadIdx.x + off];
        __syncthreads();
    }
    if (threadIdx.x == 0) {
        float ld = 0.0f;
        for (int k = 0; k < NBLK; k++) ld += g_logdet_part[s * NBLK + k];
        outL[s] = red[0] - 0.5f * (float)NCOUT * ld;
    }
}

// ---------------- launch ----------------
#define POTF2_SMEM ((2 * 128 * 129 + 3 * 32 * 33) * (int)sizeof(float))

extern "C" void kernel_launch(void* const* d_in, const int* in_sizes, int n_in,
                              void* d_out, int out_size) {
    const float* X  = (const float*)d_in[0];
    const float* u  = (const float*)d_in[1];
    const float* lp = (const float*)d_in[2];
    const float* Z  = (const float*)d_in[3];
    float* outW = (float*)d_out;
    float* outL = outW + (size_t)NS * NCOUT * DDIM;

    cudaFuncSetAttribute(potf2_kernel, cudaFuncAttributeMaxDynamicSharedMemorySize, POTF2_SMEM);
    cudaFuncSetAttribute(tc_gram_kernel, cudaFuncAttributeMaxDynamicSharedMemorySize, GRAM_SMEM);

    build_patches<<<147456, 256>>>(X, lp);
    build_yt<<<8192, 256>>>(u, lp);
    tc_gram_kernel<<<dim3(63, NS), 256, GRAM_SMEM>>>();

    for (int k = 0; k < NBLK; k++) {
        potf2_kernel<<<NS, 512, POTF2_SMEM>>>(k);
        int rem = NBLK - 1 - k;
        if (rem > 0) {
            chol_trsm_kernel<<<dim3(rem, 1, NS), 256>>>(k);
            chol_syrk_kernel<<<dim3(rem * (rem + 1) / 2, 1, NS), 256>>>(k);
        }
    }

    for (int k = 0; k < NBLK; k++) {
        fsolve_diag_kernel<<<dim3(2, 1, NS), 256>>>(k);
        if (k < NBLK - 1) fsolve_update_kernel<<<dim3(2, NBLK - 1 - k, NS), 256>>>(k);
    }
    addz_kernel<<<4608, 256>>>(Z);
    for (int k = NBLK - 1; k >= 0; k--) {
        bsolve_diag_kernel<<<dim3(2, 1, NS), 256>>>(k);
        if (k > 0) bsolve_update_kernel<<<dim3(2, k, NS), 256>>>(k);
    }

    finalize_kernel<<<4608, 256>>>(Z, outW);
    logpq_kernel<<<NS, 256>>>(outL);
}

// round 7
// speedup vs baseline: 3.5369x; 1.1076x over previous
#include <cuda_runtime.h>
#include <cuda_bf16.h>
#include <math.h>
#include <stdint.h>

// ---------------- problem constants ----------------
#define NS     4
#define NBATCH 32
#define NCIN   128
#define NCOUT  256
#define HH     16
#define WW     16
#define DDIM   1152
#define NPIX   256
#define NCOLS  8192
#define NBLK   9

// ---------------- scratch ----------------
__device__ __nv_bfloat16 g_Phi[(size_t)NS * DDIM * NCOLS];
__device__ __nv_bfloat16 g_Plo[(size_t)NS * DDIM * NCOLS];
__device__ __nv_bfloat16 g_Yhi[(size_t)NCOUT * NCOLS];
__device__ __nv_bfloat16 g_Ylo[(size_t)NCOUT * NCOLS];
__device__ float g_prec[(size_t)NS * DDIM * DDIM];
__device__ float g_R   [(size_t)NS * DDIM * NCOUT];
__device__ float g_Dinv[(size_t)NS * NBLK * 128 * 128];
__device__ float g_logdet_part[NS * NBLK];
__device__ float g_part[NS * 1152];

// ---------------- helpers ----------------
__device__ __forceinline__ uint32_t smem_u32(const void* p) {
    uint32_t a;
    asm("{ .reg .u64 t; cvta.to.shared.u64 t, %1; cvt.u32.u64 %0, t; }" : "=r"(a) : "l"(p));
    return a;
}

#define CP_ASYNC16(dst, src) \
    asm volatile("cp.async.cg.shared.global [%0], [%1], 16;" :: "r"(dst), "l"(src) : "memory")
#define CP_COMMIT() asm volatile("cp.async.commit_group;" ::: "memory")
#define CP_WAIT1()  asm volatile("cp.async.wait_group 1;" ::: "memory")

#define LDMATRIX_X4(r0, r1, r2, r3, addr) \
    asm volatile("ldmatrix.sync.aligned.m8n8.x4.shared.b16 {%0,%1,%2,%3}, [%4];" \
        : "=r"(r0), "=r"(r1), "=r"(r2), "=r"(r3) : "r"(addr))

#define MMA16816(d, a, b0, b1) \
    asm volatile("mma.sync.aligned.m16n8k16.row.col.f32.bf16.bf16.f32 " \
        "{%0,%1,%2,%3}, {%4,%5,%6,%7}, {%8,%9}, {%0,%1,%2,%3};" \
        : "+f"((d)[0]), "+f"((d)[1]), "+f"((d)[2]), "+f"((d)[3]) \
        : "r"((a)[0]), "r"((a)[1]), "r"((a)[2]), "r"((a)[3]), "r"(b0), "r"(b1))

__device__ __forceinline__ uint32_t sw128(uint32_t off) {
    return off ^ ((off >> 3) & 0x70);
}

// ---------------- patch build (bf16 hi/lo) ----------------
__global__ __launch_bounds__(256) void build_patches(const float* __restrict__ X,
                                                     const float* __restrict__ lp) {
    size_t i = (size_t)blockIdx.x * 256 + threadIdx.x;
    int n = (int)(i % NCOLS);
    size_t r = i / NCOLS;
    int d = (int)(r % DDIM);
    int s = (int)(r / DDIM);
    int b = n >> 8;
    int p = n & 255;
    int y = p >> 4, x = p & 15;
    int cin = d / 9;
    int rem = d - cin * 9;
    int kh = rem / 3, kw = rem - kh * 3;
    int yy = y + kh - 1, xx = x + kw - 1;
    float v = 0.0f;
    if (yy >= 0 && yy < HH && xx >= 0 && xx < WW) {
        float sp = expf(0.5f * lp[b]);
        v = sp * X[((((size_t)s * NBATCH + b) * NCIN + cin) * HH + yy) * WW + xx];
    }
    __nv_bfloat16 hi = __float2bfloat16_rn(v);
    g_Phi[i] = hi;
    g_Plo[i] = __float2bfloat16_rn(v - __bfloat162float(hi));
}

__global__ __launch_bounds__(256) void build_yt(const float* __restrict__ u,
                                                const float* __restrict__ lp) {
    size_t i = (size_t)blockIdx.x * 256 + threadIdx.x;
    int n = (int)(i % NCOLS);
    int c = (int)(i / NCOLS);
    int b = n >> 8;
    int p = n & 255;
    float v = expf(0.5f * lp[b]) * u[((size_t)b * NCOUT + c) * NPIX + p];
    __nv_bfloat16 hi = __float2bfloat16_rn(v);
    g_Yhi[i] = hi;
    g_Ylo[i] = __float2bfloat16_rn(v - __bfloat162float(hi));
}

// ---------------- warp-MMA Gram kernel (XLX lower tiles + XLY) ----------------
#define TILE_B 16384
#define BUF_B  65536
#define GRAM_SMEM (2 * BUF_B)

__global__ __launch_bounds__(256, 1) void tc_gram_kernel() {
    extern __shared__ char sm[];
    uint32_t smb = smem_u32(sm);
    int tid = threadIdx.x;
    int wid = tid >> 5, lid = tid & 31;
    int s = blockIdx.y;
    int t = blockIdx.x;

    const __nv_bfloat16 *Ah, *Al, *Bh, *Bl;
    float* C;
    int ldc;
    float prior;
    if (t < 45) {
        int bi = 0;
        while ((bi + 1) * (bi + 2) / 2 <= t) bi++;
        int bj = t - bi * (bi + 1) / 2;
        size_t ar = (size_t)(s * DDIM + bi * 128) * NCOLS;
        size_t br = (size_t)(s * DDIM + bj * 128) * NCOLS;
        Ah = g_Phi + ar; Al = g_Plo + ar;
        Bh = g_Phi + br; Bl = g_Plo + br;
        C = g_prec + (size_t)s * DDIM * DDIM + (size_t)bi * 128 * DDIM + bj * 128;
        ldc = DDIM;
        prior = (bi == bj) ? 1.0f : 0.0f;
    } else {
        int u2 = t - 45;
        int bi = u2 >> 1, bj = u2 & 1;
        size_t ar = (size_t)(s * DDIM + bi * 128) * NCOLS;
        size_t br = (size_t)bj * 128 * NCOLS;
        Ah = g_Phi + ar; Al = g_Plo + ar;
        Bh = g_Yhi + br; Bl = g_Ylo + br;
        C = g_R + (size_t)s * DDIM * NCOUT + (size_t)bi * 128 * NCOUT + bj * 128;
        ldc = NCOUT;
        prior = 0.0f;
    }

    int lrow[4], lseg[4];
    uint32_t lsw[4];
#pragma unroll
    for (int j = 0; j < 4; j++) {
        int idx = tid + j * 256;
        lrow[j] = idx >> 3;
        lseg[j] = idx & 7;
        lsw[j] = sw128((uint32_t)(lrow[j] * 128 + lseg[j] * 16));
    }

    float acc[2][8][4];
#pragma unroll
    for (int a = 0; a < 2; a++)
#pragma unroll
        for (int b = 0; b < 8; b++)
#pragma unroll
            for (int c = 0; c < 4; c++) acc[a][b][c] = 0.0f;

    int wm = (wid >> 1) * 32;
    int wn = (wid & 1) * 64;
    int l16 = lid & 15;
    int kseg16 = (lid >> 4) * 16;

    {
#pragma unroll
        for (int arr = 0; arr < 4; arr++) {
            const __nv_bfloat16* G = (arr == 0) ? Ah : (arr == 1) ? Al : (arr == 2) ? Bh : Bl;
#pragma unroll
            for (int j = 0; j < 4; j++)
                CP_ASYNC16(smb + arr * TILE_B + lsw[j],
                           G + (size_t)lrow[j] * NCOLS + lseg[j] * 8);
        }
        CP_COMMIT();
    }

    for (int i = 0; i < 128; i++) {
        int buf = i & 1;
        if (i + 1 < 128) {
            int k0 = (i + 1) * 64;
            uint32_t bb = smb + ((i + 1) & 1) * BUF_B;
#pragma unroll
            for (int arr = 0; arr < 4; arr++) {
                const __nv_bfloat16* G = (arr == 0) ? Ah : (arr == 1) ? Al : (arr == 2) ? Bh : Bl;
#pragma unroll
                for (int j = 0; j < 4; j++)
                    CP_ASYNC16(bb + arr * TILE_B + lsw[j],
                               G + (size_t)lrow[j] * NCOLS + k0 + lseg[j] * 8);
            }
        }
        CP_COMMIT();
        CP_WAIT1();
        __syncthreads();

        uint32_t base = smb + buf * BUF_B;
#pragma unroll
        for (int ks = 0; ks < 4; ks++) {
            int kb = ks * 32 + kseg16;
            uint32_t ah[2][4], al[2][4], bh[4][4], bl[4][4];
#pragma unroll
            for (int mb = 0; mb < 2; mb++) {
                uint32_t off = sw128((uint32_t)((wm + mb * 16 + l16) * 128 + kb));
                LDMATRIX_X4(ah[mb][0], ah[mb][1], ah[mb][2], ah[mb][3], base + off);
                LDMATRIX_X4(al[mb][0], al[mb][1], al[mb][2], al[mb][3], base + TILE_B + off);
            }
#pragma unroll
            for (int nb = 0; nb < 4; nb++) {
                uint32_t off = sw128((uint32_t)((wn + nb * 16 + l16) * 128 + kb));
                LDMATRIX_X4(bh[nb][0], bh[nb][1], bh[nb][2], bh[nb][3], base + 2 * TILE_B + off);
                LDMATRIX_X4(bl[nb][0], bl[nb][1], bl[nb][2], bl[nb][3], base + 3 * TILE_B + off);
            }
#pragma unroll
            for (int mb = 0; mb < 2; mb++)
#pragma unroll
                for (int n8 = 0; n8 < 8; n8++) {
                    int nb = n8 >> 1, h = n8 & 1;
                    MMA16816(acc[mb][n8], ah[mb], bh[nb][h], bh[nb][h + 2]);
                    MMA16816(acc[mb][n8], ah[mb], bl[nb][h], bl[nb][h + 2]);
                    MMA16816(acc[mb][n8], al[mb], bh[nb][h], bh[nb][h + 2]);
                }
        }
        __syncthreads();
    }

    int tq = lid >> 2;
    int tc2 = (lid & 3) * 2;
#pragma unroll
    for (int mb = 0; mb < 2; mb++) {
#pragma unroll
        for (int n8 = 0; n8 < 8; n8++) {
            int col = wn + n8 * 8 + tc2;
            int row0 = wm + mb * 16 + tq;
            int row1 = row0 + 8;
            float c0 = acc[mb][n8][0], c1 = acc[mb][n8][1];
            float c2 = acc[mb][n8][2], c3 = acc[mb][n8][3];
            if (prior != 0.0f) {
                if (row0 == col) c0 += prior;
                if (row0 == col + 1) c1 += prior;
                if (row1 == col) c2 += prior;
                if (row1 == col + 1) c3 += prior;
            }
            *(float2*)&C[(size_t)row0 * ldc + col] = make_float2(c0, c1);
            *(float2*)&C[(size_t)row1 * ldc + col] = make_float2(c2, c3);
        }
    }
}

// ---------------- fp32 tile FMA core (Cholesky/solve GEMMs) ----------------
__device__ __forceinline__ void mm_tile_compute(const float (*As)[128], const float (*Bs)[128],
                                                float acc[8][8], int tr, int tc) {
#pragma unroll
    for (int kk = 0; kk < 16; kk++) {
        float ra[8], rb[8];
        *(float4*)&ra[0] = *(const float4*)&As[kk][tr * 8];
        *(float4*)&ra[4] = *(const float4*)&As[kk][tr * 8 + 4];
        *(float4*)&rb[0] = *(const float4*)&Bs[kk][tc * 8];
        *(float4*)&rb[4] = *(const float4*)&Bs[kk][tc * 8 + 4];
#pragma unroll
        for (int a = 0; a < 8; a++)
#pragma unroll
            for (int b = 0; b < 8; b++)
                acc[a][b] = fmaf(ra[a], rb[b], acc[a][b]);
    }
}

template <int TA, int TB>
__device__ __forceinline__ void gemm128(const float* __restrict__ A, int lda,
                                        const float* __restrict__ Bp, int ldb,
                                        float* __restrict__ C, int ldc,
                                        float alpha, int beta) {
    __shared__ float As[16][128];
    __shared__ float Bs[16][128];
    float acc[8][8];
#pragma unroll
    for (int a = 0; a < 8; a++)
#pragma unroll
        for (int b = 0; b < 8; b++) acc[a][b] = 0.0f;
    int tid = threadIdx.x;
    int tr = tid >> 4, tc = tid & 15;

    for (int k0 = 0; k0 < 128; k0 += 16) {
#pragma unroll
        for (int q = 0; q < 2; q++) {
            int idx = tid + q * 256;
            if (TA) {
                int kk = idx >> 5, m4 = (idx & 31) << 2;
                float4 v = *(const float4*)&A[(size_t)(k0 + kk) * lda + m4];
                *(float4*)&As[kk][m4] = v;
            } else {
                int rr = idx >> 2, c4 = (idx & 3) << 2;
                float4 v = *(const float4*)&A[(size_t)rr * lda + k0 + c4];
                As[c4 + 0][rr] = v.x; As[c4 + 1][rr] = v.y;
                As[c4 + 2][rr] = v.z; As[c4 + 3][rr] = v.w;
            }
            if (TB) {
                int rr = idx >> 2, c4 = (idx & 3) << 2;
                float4 v = *(const float4*)&Bp[(size_t)rr * ldb + k0 + c4];
                Bs[c4 + 0][rr] = v.x; Bs[c4 + 1][rr] = v.y;
                Bs[c4 + 2][rr] = v.z; Bs[c4 + 3][rr] = v.w;
            } else {
                int kk = idx >> 5, m4 = (idx & 31) << 2;
                float4 v = *(const float4*)&Bp[(size_t)(k0 + kk) * ldb + m4];
                *(float4*)&Bs[kk][m4] = v;
            }
        }
        __syncthreads();
        mm_tile_compute(As, Bs, acc, tr, tc);
        __syncthreads();
    }
#pragma unroll
    for (int a = 0; a < 8; a++) {
        int row = tr * 8 + a;
#pragma unroll
        for (int b = 0; b < 8; b++) {
            int col = tc * 8 + b;
            float v = alpha * acc[a][b];
            if (beta) v += C[(size_t)row * ldc + col];
            C[(size_t)row * ldc + col] = v;
        }
    }
}

// ---------------- Cholesky diag block: register-warp factor + blocked inverse ----------------
// SMEM layout (dynamic): Ls[128][129] | Iv[128][129] | Tbuf[3][32][33]
__global__ __launch_bounds__(512) void potf2_kernel(int kb) {
    extern __shared__ float sh[];
    float (*Ls)[129] = (float(*)[129])sh;
    float (*Iv)[129] = (float(*)[129])(sh + 128 * 129);
    float (*Tbuf)[33] = (float(*)[33])(sh + 2 * 128 * 129);  // [3*32][33]
    __shared__ float red[128];
    int s = blockIdx.x;
    int tid = threadIdx.x;
    float* Ablk = g_prec + (size_t)s * DDIM * DDIM + (size_t)kb * 128 * DDIM + kb * 128;

    // load block; zero Iv
    for (int idx = tid; idx < 128 * 128; idx += 512)
        Ls[idx >> 7][idx & 127] = Ablk[(size_t)(idx >> 7) * DDIM + (idx & 127)];
    for (int idx = tid; idx < 128 * 129; idx += 512)
        ((float*)Iv)[idx] = 0.0f;
    __syncthreads();

    for (int p = 0; p < 4; p++) {
        int c0 = p * 32;
        // (a)+(b): register-resident 32x32 factor + triangular inverse (warp 0)
        if (tid < 32) {
            int r = tid;
            float row[32];
#pragma unroll
            for (int j = 0; j < 32; j++) row[j] = Ls[c0 + r][c0 + j];

            // factor: lane r owns row r
#pragma unroll
            for (int j = 0; j < 32; j++) {
                float d = __shfl_sync(0xffffffffu, row[j], j);
                float ljj = sqrtf(d);
                float inv = 1.0f / ljj;
                row[j] = (r == j) ? ljj : ((r > j) ? row[j] * inv : row[j]);
                float lrj = row[j];
#pragma unroll
                for (int c = j + 1; c < 32; c++) {
                    float lcj = __shfl_sync(0xffffffffu, row[j], c);
                    if (r >= c) row[c] -= lrj * lcj;
                }
            }
#pragma unroll
            for (int j = 0; j < 32; j++) Ls[c0 + r][c0 + j] = row[j];

            // triangular inverse: lane = column c, forward substitution in registers
            int c = r;
            float x[32];
#pragma unroll
            for (int i = 0; i < 32; i++) {
                float acc = (i == c) ? 1.0f : 0.0f;
#pragma unroll
                for (int t = 0; t < i; t++) {
                    float lit = __shfl_sync(0xffffffffu, row[t], i);
                    acc -= lit * x[t];
                }
                float lii = __shfl_sync(0xffffffffu, row[i], i);
                x[i] = acc * (1.0f / lii);
            }
#pragma unroll
            for (int i = 0; i < 32; i++) Iv[c0 + i][c0 + c] = x[i];
        }
        __syncthreads();

        if (p < 3) {
            int base = c0 + 32;
            int nrows = 128 - base;
            int nout = nrows * 32;
            // (c) TRSM: panel = panel @ inv(Ldd)^T, register-staged in-place
            float vreg[6];
            int cnt = 0;
            for (int e = tid; e < nout; e += 512, cnt++) {
                int ri = base + (e >> 5);
                int c = e & 31;
                float acc = 0.0f;
#pragma unroll
                for (int t = 0; t < 32; t++)
                    acc += Ls[ri][c0 + t] * Iv[c0 + c][c0 + t];
                vreg[cnt] = acc;
            }
            __syncthreads();
            cnt = 0;
            for (int e = tid; e < nout; e += 512, cnt++)
                Ls[base + (e >> 5)][c0 + (e & 31)] = vreg[cnt];
            __syncthreads();
            // (d) SYRK trailing (full square, symmetric), 4x4 register tiles
            int tpr = nrows >> 2;
            int ntile = tpr * tpr;
            for (int e = tid; e < ntile; e += 512) {
                int ti = e / tpr, tj = e - ti * tpr;
                int r0 = base + ti * 4, q0 = base + tj * 4;
                float accq[4][4];
#pragma unroll
                for (int a = 0; a < 4; a++)
#pragma unroll
                    for (int b = 0; b < 4; b++)
                        accq[a][b] = Ls[r0 + a][q0 + b];
#pragma unroll
                for (int t = 0; t < 32; t++) {
                    float av[4], bv[4];
#pragma unroll
                    for (int a = 0; a < 4; a++) av[a] = Ls[r0 + a][c0 + t];
#pragma unroll
                    for (int b = 0; b < 4; b++) bv[b] = Ls[q0 + b][c0 + t];
#pragma unroll
                    for (int a = 0; a < 4; a++)
#pragma unroll
                        for (int b = 0; b < 4; b++)
                            accq[a][b] -= av[a] * bv[b];
                }
#pragma unroll
                for (int a = 0; a < 4; a++)
#pragma unroll
                    for (int b = 0; b < 4; b++)
                        Ls[r0 + a][q0 + b] = accq[a][b];
            }
            __syncthreads();
        }
    }

    // logdet partials
    if (tid < 128) red[tid] = 2.0f * logf(Ls[tid][tid]);
    __syncthreads();
    for (int off = 64; off; off >>= 1) {
        if (tid < off) red[tid] += red[tid + off];
        __syncthreads();
    }
    if (tid == 0) g_logdet_part[s * NBLK + kb] = red[0];

    // compose full 128x128 inverse: M_ij = -Dinv_ii @ (sum_t L_it M_tj)
    int grp = tid >> 7;       // 0..3  (block column j = grp)
    int gt = tid & 127;
    int tr = gt >> 4;         // 0..7 -> rows tr*4..tr*4+3
    int tcg = gt & 15;        // cols tcg*2, tcg*2+1
    for (int step = 1; step <= 3; step++) {
        int j = grp, i = grp + step;
        bool act = (i <= 3);
        if (act) {
            float acc[4][2];
#pragma unroll
            for (int a = 0; a < 4; a++) { acc[a][0] = 0.0f; acc[a][1] = 0.0f; }
            for (int t = j; t < i; t++) {
#pragma unroll 1
                for (int u = 0; u < 32; u++) {
                    float b0 = Iv[32 * t + u][32 * j + tcg * 2];
                    float b1 = Iv[32 * t + u][32 * j + tcg * 2 + 1];
#pragma unroll
                    for (int a = 0; a < 4; a++) {
                        float av = Ls[32 * i + tr * 4 + a][32 * t + u];
                        acc[a][0] += av * b0;
                        acc[a][1] += av * b1;
                    }
                }
            }
#pragma unroll
            for (int a = 0; a < 4; a++) {
                Tbuf[grp * 32 + tr * 4 + a][tcg * 2]     = acc[a][0];
                Tbuf[grp * 32 + tr * 4 + a][tcg * 2 + 1] = acc[a][1];
            }
        }
        __syncthreads();
        if (act) {
            float acc[4][2];
#pragma unroll
            for (int a = 0; a < 4; a++) { acc[a][0] = 0.0f; acc[a][1] = 0.0f; }
#pragma unroll 1
            for (int u = 0; u < 32; u++) {
                float b0 = Tbuf[grp * 32 + u][tcg * 2];
                float b1 = Tbuf[grp * 32 + u][tcg * 2 + 1];
#pragma unroll
                for (int a = 0; a < 4; a++) {
                    float av = Iv[32 * i + tr * 4 + a][32 * i + u];
                    acc[a][0] += av * b0;
                    acc[a][1] += av * b1;
                }
            }
#pragma unroll
            for (int a = 0; a < 4; a++) {
                Iv[32 * i + tr * 4 + a][32 * j + tcg * 2]     = -acc[a][0];
                Iv[32 * i + tr * 4 + a][32 * j + tcg * 2 + 1] = -acc[a][1];
            }
        }
        __syncthreads();
    }

    // write Dinv
    float* Dst = g_Dinv + ((size_t)s * NBLK + kb) * 128 * 128;
    for (int idx = tid; idx < 128 * 128; idx += 512)
        Dst[idx] = Iv[idx >> 7][idx & 127];
}

__global__ __launch_bounds__(256) void chol_trsm_kernel(int k) {
    int s = blockIdx.z;
    int i = k + 1 + blockIdx.x;
    float* Ablk = g_prec + (size_t)s * DDIM * DDIM + (size_t)i * 128 * DDIM + k * 128;
    const float* Dinv = g_Dinv + ((size_t)s * NBLK + k) * 128 * 128;
    gemm128<0, 1>(Ablk, DDIM, Dinv, 128, Ablk, DDIM, 1.0f, 0);
}

__global__ __launch_bounds__(256) void chol_syrk_kernel(int k) {
    int s = blockIdx.z;
    int t = blockIdx.x;
    int a = 0;
    while ((a + 1) * (a + 2) / 2 <= t) a++;
    int b = t - a * (a + 1) / 2;
    int i = k + 1 + a, j = k + 1 + b;
    const float* Aik = g_prec + (size_t)s * DDIM * DDIM + (size_t)i * 128 * DDIM + k * 128;
    const float* Ajk = g_prec + (size_t)s * DDIM * DDIM + (size_t)j * 128 * DDIM + k * 128;
    float* Cij = g_prec + (size_t)s * DDIM * DDIM + (size_t)i * 128 * DDIM + j * 128;
    gemm128<0, 1>(Aik, DDIM, Ajk, DDIM, Cij, DDIM, -1.0f, 1);
}

// ---------------- triangular solves ----------------
__global__ __launch_bounds__(256) void fsolve_diag_kernel(int k) {
    int s = blockIdx.z;
    int ct = blockIdx.x;
    float* Rk = g_R + (size_t)s * DDIM * NCOUT + (size_t)k * 128 * NCOUT + ct * 128;
    const float* Dinv = g_Dinv + ((size_t)s * NBLK + k) * 128 * 128;
    gemm128<0, 0>(Dinv, 128, Rk, NCOUT, Rk, NCOUT, 1.0f, 0);
}

__global__ __launch_bounds__(256) void fsolve_update_kernel(int k) {
    int s = blockIdx.z;
    int ct = blockIdx.x;
    int i = k + 1 + blockIdx.y;
    const float* A = g_prec + (size_t)s * DDIM * DDIM + (size_t)i * 128 * DDIM + k * 128;
    const float* Rk = g_R + (size_t)s * DDIM * NCOUT + (size_t)k * 128 * NCOUT + ct * 128;
    float* Ri = g_R + (size_t)s * DDIM * NCOUT + (size_t)i * 128 * NCOUT + ct * 128;
    gemm128<0, 0>(A, DDIM, Rk, NCOUT, Ri, NCOUT, -1.0f, 1);
}

__global__ __launch_bounds__(256) void addz_kernel(const float* __restrict__ Z) {
    size_t i = (size_t)blockIdx.x * 256 + threadIdx.x;
    int c = (int)(i % NCOUT);
    size_t r = i / NCOUT;
    int d = (int)(r % DDIM);
    int s = (int)(r / DDIM);
    g_R[i] += Z[((size_t)s * NCOUT + c) * DDIM + d];
}

__global__ __launch_bounds__(256) void bsolve_diag_kernel(int k) {
    int s = blockIdx.z;
    int ct = blockIdx.x;
    float* Rk = g_R + (size_t)s * DDIM * NCOUT + (size_t)k * 128 * NCOUT + ct * 128;
    const float* Dinv = g_Dinv + ((size_t)s * NBLK + k) * 128 * 128;
    gemm128<1, 0>(Dinv, 128, Rk, NCOUT, Rk, NCOUT, 1.0f, 0);
}

__global__ __launch_bounds__(256) void bsolve_update_kernel(int k) {
    int s = blockIdx.z;
    int ct = blockIdx.x;
    int i = blockIdx.y;
    const float* A = g_prec + (size_t)s * DDIM * DDIM + (size_t)k * 128 * DDIM + i * 128;
    const float* Rk = g_R + (size_t)s * DDIM * NCOUT + (size_t)k * 128 * NCOUT + ct * 128;
    float* Ri = g_R + (size_t)s * DDIM * NCOUT + (size_t)i * 128 * NCOUT + ct * 128;
    gemm128<1, 0>(A, DDIM, Rk, NCOUT, Ri, NCOUT, -1.0f, 1);
}

// ---------------- output + reductions ----------------
__global__ __launch_bounds__(256) void finalize_kernel(const float* __restrict__ Z,
                                                       float* __restrict__ outW) {
    __shared__ float red[256];
    size_t i = (size_t)blockIdx.x * 256 + threadIdx.x;
    int d = (int)(i % DDIM);
    size_t r = i / DDIM;
    int c = (int)(r % NCOUT);
    int s = (int)(r / NCOUT);
    float w = g_R[((size_t)s * DDIM + d) * NCOUT + c];
    outW[i] = w;
    float z = Z[i];
    red[threadIdx.x] = 0.5f * z * z - 0.5f * w * w;
    __syncthreads();
    for (int off = 128; off; off >>= 1) {
        if (threadIdx.x < off) red[threadIdx.x] += red[threadIdx.x + off];
        __syncthreads();
    }
    if (threadIdx.x == 0) g_part[blockIdx.x] = red[0];
}

__global__ __launch_bounds__(256) void logpq_kernel(float* __restrict__ outL) {
    __shared__ float red[256];
    int s = blockIdx.x;
    float acc = 0.0f;
    for (int i = threadIdx.x; i < 1152; i += 256) acc += g_part[s * 1152 + i];
    red[threadIdx.x] = acc;
    __syncthreads();
    for (int off = 128; off; off >>= 1) {
        if (threadIdx.x < off) red[threadIdx.x] += red[threadIdx.x + off];
        __syncthreads();
    }
    if (threadIdx.x == 0) {
        float ld = 0.0f;
        for (int k = 0; k < NBLK; k++) ld += g_logdet_part[s * NBLK + k];
        outL[s] = red[0] - 0.5f * (float)NCOUT * ld;
    }
}

// ---------------- launch ----------------
#define POTF2_SMEM ((2 * 128 * 129 + 3 * 32 * 33) * (int)sizeof(float))

extern "C" void kernel_launch(void* const* d_in, const int* in_sizes, int n_in,
                              void* d_out, int out_size) {
    const float* X  = (const float*)d_in[0];
    const float* u  = (const float*)d_in[1];
    const float* lp = (const float*)d_in[2];
    const float* Z  = (const float*)d_in[3];
    float* outW = (float*)d_out;
    float* outL = outW + (size_t)NS * NCOUT * DDIM;

    cudaFuncSetAttribute(potf2_kernel, cudaFuncAttributeMaxDynamicSharedMemorySize, POTF2_SMEM);
    cudaFuncSetAttribute(tc_gram_kernel, cudaFuncAttributeMaxDynamicSharedMemorySize, GRAM_SMEM);

    build_patches<<<147456, 256>>>(X, lp);
    build_yt<<<8192, 256>>>(u, lp);
    tc_gram_kernel<<<dim3(63, NS), 256, GRAM_SMEM>>>();

    for (int k = 0; k < NBLK; k++) {
        potf2_kernel<<<NS, 512, POTF2_SMEM>>>(k);
        int rem = NBLK - 1 - k;
        if (rem > 0) {
            chol_trsm_kernel<<<dim3(rem, 1, NS), 256>>>(k);
            chol_syrk_kernel<<<dim3(rem * (rem + 1) / 2, 1, NS), 256>>>(k);
        }
    }

    for (int k = 0; k < NBLK; k++) {
        fsolve_diag_kernel<<<dim3(2, 1, NS), 256>>>(k);
        if (k < NBLK - 1) fsolve_update_kernel<<<dim3(2, NBLK - 1 - k, NS), 256>>>(k);
    }
    addz_kernel<<<4608, 256>>>(Z);
    for (int k = NBLK - 1; k >= 0; k--) {
        bsolve_diag_kernel<<<dim3(2, 1, NS), 256>>>(k);
        if (k > 0) bsolve_update_kernel<<<dim3(2, k, NS), 256>>>(k);
    }

    finalize_kernel<<<4608, 256>>>(Z, outW);
    logpq_kernel<<<NS, 256>>>(outL);
}

// round 10
// speedup vs baseline: 4.0935x; 1.1573x over previous
#include <cuda_runtime.h>
#include <cuda_bf16.h>
#include <math.h>
#include <stdint.h>

// ---------------- problem constants ----------------
#define NS     4
#define NBATCH 32
#define NCIN   128
#define NCOUT  256
#define HH     16
#define WW     16
#define DDIM   1152
#define NPIX   256
#define NCOLS  8192
#define NBLK   9
#define DD2    (DDIM * DDIM)
#define DR     (DDIM * NCOUT)

// ---------------- scratch ----------------
__device__ __nv_bfloat16 g_Phi[(size_t)NS * DDIM * NCOLS];
__device__ __nv_bfloat16 g_Plo[(size_t)NS * DDIM * NCOLS];
__device__ __nv_bfloat16 g_Yhi[(size_t)NCOUT * NCOLS];
__device__ __nv_bfloat16 g_Ylo[(size_t)NCOUT * NCOLS];
__device__ float g_prec[(size_t)NS * DD2];
__device__ float g_M   [(size_t)NS * DD2];     // explicit block lower inverse of L
__device__ float g_S   [(size_t)NS * DD2];     // substitution accumulators
__device__ float g_R   [(size_t)NS * DR];      // XLY -> Wm^T
__device__ float g_T   [(size_t)NS * DR];      // forward-solve temp
__device__ float g_Dinv[(size_t)NS * NBLK * 128 * 128];
__device__ float g_logdet_part[NS * NBLK];
__device__ float g_part[NS * 1152];

// ---------------- helpers ----------------
__device__ __forceinline__ uint32_t smem_u32(const void* p) {
    uint32_t a;
    asm("{ .reg .u64 t; cvta.to.shared.u64 t, %1; cvt.u32.u64 %0, t; }" : "=r"(a) : "l"(p));
    return a;
}

#define CP_ASYNC16(dst, src) \
    asm volatile("cp.async.cg.shared.global [%0], [%1], 16;" :: "r"(dst), "l"(src) : "memory")
#define CP_COMMIT() asm volatile("cp.async.commit_group;" ::: "memory")
#define CP_WAIT1()  asm volatile("cp.async.wait_group 1;" ::: "memory")

#define LDMATRIX_X4(r0, r1, r2, r3, addr) \
    asm volatile("ldmatrix.sync.aligned.m8n8.x4.shared.b16 {%0,%1,%2,%3}, [%4];" \
        : "=r"(r0), "=r"(r1), "=r"(r2), "=r"(r3) : "r"(addr))

#define MMA16816(d, a, b0, b1) \
    asm volatile("mma.sync.aligned.m16n8k16.row.col.f32.bf16.bf16.f32 " \
        "{%0,%1,%2,%3}, {%4,%5,%6,%7}, {%8,%9}, {%0,%1,%2,%3};" \
        : "+f"((d)[0]), "+f"((d)[1]), "+f"((d)[2]), "+f"((d)[3]) \
        : "r"((a)[0]), "r"((a)[1]), "r"((a)[2]), "r"((a)[3]), "r"(b0), "r"(b1))

__device__ __forceinline__ uint32_t sw128(uint32_t off) {
    return off ^ ((off >> 3) & 0x70);
}

// ---------------- patch build (bf16 hi/lo) ----------------
__global__ __launch_bounds__(256) void build_patches(const float* __restrict__ X,
                                                     const float* __restrict__ lp) {
    size_t i = (size_t)blockIdx.x * 256 + threadIdx.x;
    int n = (int)(i % NCOLS);
    size_t r = i / NCOLS;
    int d = (int)(r % DDIM);
    int s = (int)(r / DDIM);
    int b = n >> 8;
    int p = n & 255;
    int y = p >> 4, x = p & 15;
    int cin = d / 9;
    int rem = d - cin * 9;
    int kh = rem / 3, kw = rem - kh * 3;
    int yy = y + kh - 1, xx = x + kw - 1;
    float v = 0.0f;
    if (yy >= 0 && yy < HH && xx >= 0 && xx < WW) {
        float sp = expf(0.5f * lp[b]);
        v = sp * X[((((size_t)s * NBATCH + b) * NCIN + cin) * HH + yy) * WW + xx];
    }
    __nv_bfloat16 hi = __float2bfloat16_rn(v);
    g_Phi[i] = hi;
    g_Plo[i] = __float2bfloat16_rn(v - __bfloat162float(hi));
}

__global__ __launch_bounds__(256) void build_yt(const float* __restrict__ u,
                                                const float* __restrict__ lp) {
    size_t i = (size_t)blockIdx.x * 256 + threadIdx.x;
    int n = (int)(i % NCOLS);
    int c = (int)(i / NCOLS);
    int b = n >> 8;
    int p = n & 255;
    float v = expf(0.5f * lp[b]) * u[((size_t)b * NCOUT + c) * NPIX + p];
    __nv_bfloat16 hi = __float2bfloat16_rn(v);
    g_Yhi[i] = hi;
    g_Ylo[i] = __float2bfloat16_rn(v - __bfloat162float(hi));
}

__global__ __launch_bounds__(256) void zero_s_kernel() {
    size_t i = (size_t)blockIdx.x * 256 + threadIdx.x;
    ((float4*)g_S)[i] = make_float4(0.f, 0.f, 0.f, 0.f);
}

// ---------------- warp-MMA Gram kernel (XLX lower tiles + XLY) ----------------
#define TILE_B 16384
#define BUF_B  65536
#define GRAM_SMEM (2 * BUF_B)

__global__ __launch_bounds__(256, 1) void tc_gram_kernel() {
    extern __shared__ char sm[];
    uint32_t smb = smem_u32(sm);
    int tid = threadIdx.x;
    int wid = tid >> 5, lid = tid & 31;
    int s = blockIdx.y;
    int t = blockIdx.x;

    const __nv_bfloat16 *Ah, *Al, *Bh, *Bl;
    float* C;
    int ldc;
    float prior;
    if (t < 45) {
        int bi = 0;
        while ((bi + 1) * (bi + 2) / 2 <= t) bi++;
        int bj = t - bi * (bi + 1) / 2;
        size_t ar = (size_t)(s * DDIM + bi * 128) * NCOLS;
        size_t br = (size_t)(s * DDIM + bj * 128) * NCOLS;
        Ah = g_Phi + ar; Al = g_Plo + ar;
        Bh = g_Phi + br; Bl = g_Plo + br;
        C = g_prec + (size_t)s * DD2 + (size_t)bi * 128 * DDIM + bj * 128;
        ldc = DDIM;
        prior = (bi == bj) ? 1.0f : 0.0f;
    } else {
        int u2 = t - 45;
        int bi = u2 >> 1, bj = u2 & 1;
        size_t ar = (size_t)(s * DDIM + bi * 128) * NCOLS;
        size_t br = (size_t)bj * 128 * NCOLS;
        Ah = g_Phi + ar; Al = g_Plo + ar;
        Bh = g_Yhi + br; Bl = g_Ylo + br;
        C = g_R + (size_t)s * DR + (size_t)bi * 128 * NCOUT + bj * 128;
        ldc = NCOUT;
        prior = 0.0f;
    }

    int lrow[4], lseg[4];
    uint32_t lsw[4];
#pragma unroll
    for (int j = 0; j < 4; j++) {
        int idx = tid + j * 256;
        lrow[j] = idx >> 3;
        lseg[j] = idx & 7;
        lsw[j] = sw128((uint32_t)(lrow[j] * 128 + lseg[j] * 16));
    }

    float acc[2][8][4];
#pragma unroll
    for (int a = 0; a < 2; a++)
#pragma unroll
        for (int b = 0; b < 8; b++)
#pragma unroll
            for (int c = 0; c < 4; c++) acc[a][b][c] = 0.0f;

    int wm = (wid >> 1) * 32;
    int wn = (wid & 1) * 64;
    int l16 = lid & 15;
    int kseg16 = (lid >> 4) * 16;

    {
#pragma unroll
        for (int arr = 0; arr < 4; arr++) {
            const __nv_bfloat16* G = (arr == 0) ? Ah : (arr == 1) ? Al : (arr == 2) ? Bh : Bl;
#pragma unroll
            for (int j = 0; j < 4; j++)
                CP_ASYNC16(smb + arr * TILE_B + lsw[j],
                           G + (size_t)lrow[j] * NCOLS + lseg[j] * 8);
        }
        CP_COMMIT();
    }

    for (int i = 0; i < 128; i++) {
        int buf = i & 1;
        if (i + 1 < 128) {
            int k0 = (i + 1) * 64;
            uint32_t bb = smb + ((i + 1) & 1) * BUF_B;
#pragma unroll
            for (int arr = 0; arr < 4; arr++) {
                const __nv_bfloat16* G = (arr == 0) ? Ah : (arr == 1) ? Al : (arr == 2) ? Bh : Bl;
#pragma unroll
                for (int j = 0; j < 4; j++)
                    CP_ASYNC16(bb + arr * TILE_B + lsw[j],
                               G + (size_t)lrow[j] * NCOLS + k0 + lseg[j] * 8);
            }
        }
        CP_COMMIT();
        CP_WAIT1();
        __syncthreads();

        uint32_t base = smb + buf * BUF_B;
#pragma unroll
        for (int ks = 0; ks < 4; ks++) {
            int kb = ks * 32 + kseg16;
            uint32_t ah[2][4], al[2][4], bh[4][4], bl[4][4];
#pragma unroll
            for (int mb = 0; mb < 2; mb++) {
                uint32_t off = sw128((uint32_t)((wm + mb * 16 + l16) * 128 + kb));
                LDMATRIX_X4(ah[mb][0], ah[mb][1], ah[mb][2], ah[mb][3], base + off);
                LDMATRIX_X4(al[mb][0], al[mb][1], al[mb][2], al[mb][3], base + TILE_B + off);
            }
#pragma unroll
            for (int nb = 0; nb < 4; nb++) {
                uint32_t off = sw128((uint32_t)((wn + nb * 16 + l16) * 128 + kb));
                LDMATRIX_X4(bh[nb][0], bh[nb][1], bh[nb][2], bh[nb][3], base + 2 * TILE_B + off);
                LDMATRIX_X4(bl[nb][0], bl[nb][1], bl[nb][2], bl[nb][3], base + 3 * TILE_B + off);
            }
#pragma unroll
            for (int mb = 0; mb < 2; mb++)
#pragma unroll
                for (int n8 = 0; n8 < 8; n8++) {
                    int nb = n8 >> 1, h = n8 & 1;
                    MMA16816(acc[mb][n8], ah[mb], bh[nb][h], bh[nb][h + 2]);
                    MMA16816(acc[mb][n8], ah[mb], bl[nb][h], bl[nb][h + 2]);
                    MMA16816(acc[mb][n8], al[mb], bh[nb][h], bh[nb][h + 2]);
                }
        }
        __syncthreads();
    }

    int tq = lid >> 2;
    int tc2 = (lid & 3) * 2;
#pragma unroll
    for (int mb = 0; mb < 2; mb++) {
#pragma unroll
        for (int n8 = 0; n8 < 8; n8++) {
            int col = wn + n8 * 8 + tc2;
            int row0 = wm + mb * 16 + tq;
            int row1 = row0 + 8;
            float c0 = acc[mb][n8][0], c1 = acc[mb][n8][1];
            float c2 = acc[mb][n8][2], c3 = acc[mb][n8][3];
            if (prior != 0.0f) {
                if (row0 == col) c0 += prior;
                if (row0 == col + 1) c1 += prior;
                if (row1 == col) c2 += prior;
                if (row1 == col + 1) c3 += prior;
            }
            *(float2*)&C[(size_t)row0 * ldc + col] = make_float2(c0, c1);
            *(float2*)&C[(size_t)row1 * ldc + col] = make_float2(c2, c3);
        }
    }
}

// ---------------- fp32 tile GEMM cores ----------------
__device__ __forceinline__ void mm_tile_compute(const float (*As)[128], const float (*Bs)[128],
                                                float acc[8][8], int tr, int tc) {
#pragma unroll
    for (int kk = 0; kk < 16; kk++) {
        float ra[8], rb[8];
        *(float4*)&ra[0] = *(const float4*)&As[kk][tr * 8];
        *(float4*)&ra[4] = *(const float4*)&As[kk][tr * 8 + 4];
        *(float4*)&rb[0] = *(const float4*)&Bs[kk][tc * 8];
        *(float4*)&rb[4] = *(const float4*)&Bs[kk][tc * 8 + 4];
#pragma unroll
        for (int a = 0; a < 8; a++)
#pragma unroll
            for (int b = 0; b < 8; b++)
                acc[a][b] = fmaf(ra[a], rb[b], acc[a][b]);
    }
}

// C(128x128) = alpha * opA(A) @ opB(B) + beta*C, K variable (multiple of 16)
template <int TA, int TB>
__device__ __forceinline__ void gemmK(const float* __restrict__ A, int lda,
                                      const float* __restrict__ Bp, int ldb,
                                      float* __restrict__ C, int ldc,
                                      int Kdim, float alpha, int beta) {
    __shared__ float As[16][128];
    __shared__ float Bs[16][128];
    float acc[8][8];
#pragma unroll
    for (int a = 0; a < 8; a++)
#pragma unroll
        for (int b = 0; b < 8; b++) acc[a][b] = 0.0f;
    int tid = threadIdx.x;
    int tr = tid >> 4, tc = tid & 15;

    for (int k0 = 0; k0 < Kdim; k0 += 16) {
#pragma unroll
        for (int q = 0; q < 2; q++) {
            int idx = tid + q * 256;
            if (TA) {
                int kk = idx >> 5, m4 = (idx & 31) << 2;
                float4 v = *(const float4*)&A[(size_t)(k0 + kk) * lda + m4];
                *(float4*)&As[kk][m4] = v;
            } else {
                int rr = idx >> 2, c4 = (idx & 3) << 2;
                float4 v = *(const float4*)&A[(size_t)rr * lda + k0 + c4];
                As[c4 + 0][rr] = v.x; As[c4 + 1][rr] = v.y;
                As[c4 + 2][rr] = v.z; As[c4 + 3][rr] = v.w;
            }
            if (TB) {
                int rr = idx >> 2, c4 = (idx & 3) << 2;
                float4 v = *(const float4*)&Bp[(size_t)rr * ldb + k0 + c4];
                Bs[c4 + 0][rr] = v.x; Bs[c4 + 1][rr] = v.y;
                Bs[c4 + 2][rr] = v.z; Bs[c4 + 3][rr] = v.w;
            } else {
                int kk = idx >> 5, m4 = (idx & 31) << 2;
                float4 v = *(const float4*)&Bp[(size_t)(k0 + kk) * ldb + m4];
                *(float4*)&Bs[kk][m4] = v;
            }
        }
        __syncthreads();
        mm_tile_compute(As, Bs, acc, tr, tc);
        __syncthreads();
    }
#pragma unroll
    for (int a = 0; a < 8; a++) {
        int row = tr * 8 + a;
#pragma unroll
        for (int b = 0; b < 8; b++) {
            int col = tc * 8 + b;
            float v = alpha * acc[a][b];
            if (beta) v += C[(size_t)row * ldc + col];
            C[(size_t)row * ldc + col] = v;
        }
    }
}

// C(128x64) = opA(A) @ B + optional Z^T add; 256 threads, 8x4 per thread
template <int TA>
__device__ __forceinline__ void gemmK64(const float* __restrict__ A, int lda,
                                        const float* __restrict__ Bp, int ldb,
                                        float* __restrict__ C, int ldc,
                                        int Kdim, const float* __restrict__ Zp) {
    __shared__ float As[16][128];
    __shared__ float Bs[16][64];
    float acc[8][4];
#pragma unroll
    for (int a = 0; a < 8; a++)
#pragma unroll
        for (int b = 0; b < 4; b++) acc[a][b] = 0.0f;
    int tid = threadIdx.x;
    int tr = tid >> 4, tc = tid & 15;

    for (int k0 = 0; k0 < Kdim; k0 += 16) {
#pragma unroll
        for (int q = 0; q < 2; q++) {
            int idx = tid + q * 256;
            if (TA) {
                int kk = idx >> 5, m4 = (idx & 31) << 2;
                float4 v = *(const float4*)&A[(size_t)(k0 + kk) * lda + m4];
                *(float4*)&As[kk][m4] = v;
            } else {
                int rr = idx >> 2, c4 = (idx & 3) << 2;
                float4 v = *(const float4*)&A[(size_t)rr * lda + k0 + c4];
                As[c4 + 0][rr] = v.x; As[c4 + 1][rr] = v.y;
                As[c4 + 2][rr] = v.z; As[c4 + 3][rr] = v.w;
            }
        }
        {
            int kk = tid >> 4, n4 = (tid & 15) << 2;
            float4 v = *(const float4*)&Bp[(size_t)(k0 + kk) * ldb + n4];
            *(float4*)&Bs[kk][n4] = v;
        }
        __syncthreads();
#pragma unroll
        for (int kk = 0; kk < 16; kk++) {
            float ra[8], rb[4];
            *(float4*)&ra[0] = *(const float4*)&As[kk][tr * 8];
            *(float4*)&ra[4] = *(const float4*)&As[kk][tr * 8 + 4];
            *(float4*)&rb[0] = *(const float4*)&Bs[kk][tc * 4];
#pragma unroll
            for (int a = 0; a < 8; a++)
#pragma unroll
                for (int b = 0; b < 4; b++)
                    acc[a][b] = fmaf(ra[a], rb[b], acc[a][b]);
        }
        __syncthreads();
    }
#pragma unroll
    for (int a = 0; a < 8; a++) {
        int row = tr * 8 + a;
        float4 v = make_float4(acc[a][0], acc[a][1], acc[a][2], acc[a][3]);
        if (Zp) {
            int col = tc * 4;
            v.x += Zp[(size_t)(col + 0) * DDIM + row];
            v.y += Zp[(size_t)(col + 1) * DDIM + row];
            v.z += Zp[(size_t)(col + 2) * DDIM + row];
            v.w += Zp[(size_t)(col + 3) * DDIM + row];
        }
        *(float4*)&C[(size_t)row * ldc + tc * 4] = v;
    }
}

// ---------------- Cholesky diag block (grid padded to 148 to dodge low-grid throttle) ----------------
__global__ __launch_bounds__(512) void potf2_kernel(int kb) {
    if (blockIdx.x >= NS) return;
    extern __shared__ float sh[];
    float (*Ls)[129] = (float(*)[129])sh;
    float (*Iv)[129] = (float(*)[129])(sh + 128 * 129);
    float (*Tbuf)[33] = (float(*)[33])(sh + 2 * 128 * 129);
    __shared__ float red[128];
    int s = blockIdx.x;
    int tid = threadIdx.x;
    float* Ablk = g_prec + (size_t)s * DD2 + (size_t)kb * 128 * DDIM + kb * 128;

    for (int idx = tid; idx < 128 * 128; idx += 512)
        Ls[idx >> 7][idx & 127] = Ablk[(size_t)(idx >> 7) * DDIM + (idx & 127)];
    for (int idx = tid; idx < 128 * 129; idx += 512)
        ((float*)Iv)[idx] = 0.0f;
    __syncthreads();

#pragma unroll
    for (int p = 0; p < 4; p++) {
        int c0 = p * 32;
        if (tid < 32) {
            int r = tid;
            float row[32];
#pragma unroll
            for (int j = 0; j < 32; j++) row[j] = Ls[c0 + r][c0 + j];
#pragma unroll
            for (int j = 0; j < 32; j++) {
                float d = __shfl_sync(0xffffffffu, row[j], j);
                float ljj = sqrtf(d);
                float inv = 1.0f / ljj;
                row[j] = (r == j) ? ljj : ((r > j) ? row[j] * inv : row[j]);
                float lrj = row[j];
#pragma unroll
                for (int c = j + 1; c < 32; c++) {
                    float lcj = __shfl_sync(0xffffffffu, row[j], c);
                    if (r >= c) row[c] -= lrj * lcj;
                }
            }
#pragma unroll
            for (int j = 0; j < 32; j++) Ls[c0 + r][c0 + j] = row[j];

            int c = r;
            float x[32];
#pragma unroll
            for (int i = 0; i < 32; i++) {
                float acc = (i == c) ? 1.0f : 0.0f;
#pragma unroll
                for (int t = 0; t < i; t++) {
                    float lit = __shfl_sync(0xffffffffu, row[t], i);
                    acc -= lit * x[t];
                }
                float lii = __shfl_sync(0xffffffffu, row[i], i);
                x[i] = acc * (1.0f / lii);
            }
#pragma unroll
            for (int i = 0; i < 32; i++) Iv[c0 + i][c0 + c] = x[i];
        }
        __syncthreads();

        if (p < 3) {
            const int base = c0 + 32;
            const int nrows = 128 - base;
            const int nout = nrows * 32;
            float vreg[6];
            int cnt = 0;
            for (int e = tid; e < nout; e += 512, cnt++) {
                int ri = base + (e >> 5);
                int c = e & 31;
                float acc = 0.0f;
#pragma unroll
                for (int t = 0; t < 32; t++)
                    acc += Ls[ri][c0 + t] * Iv[c0 + c][c0 + t];
                vreg[cnt] = acc;
            }
            __syncthreads();
            cnt = 0;
            for (int e = tid; e < nout; e += 512, cnt++)
                Ls[base + (e >> 5)][c0 + (e & 31)] = vreg[cnt];
            __syncthreads();
            const int tpr = nrows >> 2;
            const int ntile = tpr * tpr;
            for (int e = tid; e < ntile; e += 512) {
                int ti = e / tpr, tj = e - ti * tpr;
                int r0 = base + ti * 4, q0 = base + tj * 4;
                float accq[4][4];
#pragma unroll
                for (int a = 0; a < 4; a++)
#pragma unroll
                    for (int b = 0; b < 4; b++)
                        accq[a][b] = Ls[r0 + a][q0 + b];
#pragma unroll
                for (int t = 0; t < 32; t++) {
                    float av[4], bv[4];
#pragma unroll
                    for (int a = 0; a < 4; a++) av[a] = Ls[r0 + a][c0 + t];
#pragma unroll
                    for (int b = 0; b < 4; b++) bv[b] = Ls[q0 + b][c0 + t];
#pragma unroll
                    for (int a = 0; a < 4; a++)
#pragma unroll
                        for (int b = 0; b < 4; b++)
                            accq[a][b] -= av[a] * bv[b];
                }
#pragma unroll
                for (int a = 0; a < 4; a++)
#pragma unroll
                    for (int b = 0; b < 4; b++)
                        Ls[r0 + a][q0 + b] = accq[a][b];
            }
            __syncthreads();
        }
    }

    if (tid < 128) red[tid] = 2.0f * logf(Ls[tid][tid]);
    __syncthreads();
    for (int off = 64; off; off >>= 1) {
        if (tid < off) red[tid] += red[tid + off];
        __syncthreads();
    }
    if (tid == 0) g_logdet_part[s * NBLK + kb] = red[0];

    // compose full 128x128 inverse
    int grp = tid >> 7;
    int gt = tid & 127;
    int tr = gt >> 4;
    int tcg = gt & 15;
    for (int step = 1; step <= 3; step++) {
        int j = grp, i = grp + step;
        bool act = (i <= 3);
        if (act) {
            float acc[4][2];
#pragma unroll
            for (int a = 0; a < 4; a++) { acc[a][0] = 0.0f; acc[a][1] = 0.0f; }
            for (int t = j; t < i; t++) {
#pragma unroll 1
                for (int u = 0; u < 32; u++) {
                    float b0 = Iv[32 * t + u][32 * j + tcg * 2];
                    float b1 = Iv[32 * t + u][32 * j + tcg * 2 + 1];
#pragma unroll
                    for (int a = 0; a < 4; a++) {
                        float av = Ls[32 * i + tr * 4 + a][32 * t + u];
                        acc[a][0] += av * b0;
                        acc[a][1] += av * b1;
                    }
                }
            }
#pragma unroll
            for (int a = 0; a < 4; a++) {
                Tbuf[grp * 32 + tr * 4 + a][tcg * 2]     = acc[a][0];
                Tbuf[grp * 32 + tr * 4 + a][tcg * 2 + 1] = acc[a][1];
            }
        }
        __syncthreads();
        if (act) {
            float acc[4][2];
#pragma unroll
            for (int a = 0; a < 4; a++) { acc[a][0] = 0.0f; acc[a][1] = 0.0f; }
#pragma unroll 1
            for (int u = 0; u < 32; u++) {
                float b0 = Tbuf[grp * 32 + u][tcg * 2];
                float b1 = Tbuf[grp * 32 + u][tcg * 2 + 1];
#pragma unroll
                for (int a = 0; a < 4; a++) {
                    float av = Iv[32 * i + tr * 4 + a][32 * i + u];
                    acc[a][0] += av * b0;
                    acc[a][1] += av * b1;
                }
            }
#pragma unroll
            for (int a = 0; a < 4; a++) {
                Iv[32 * i + tr * 4 + a][32 * j + tcg * 2]     = -acc[a][0];
                Iv[32 * i + tr * 4 + a][32 * j + tcg * 2 + 1] = -acc[a][1];
            }
        }
        __syncthreads();
    }

    float* Dst = g_Dinv + ((size_t)s * NBLK + kb) * 16384;
    for (int idx = tid; idx < 128 * 128; idx += 512)
        Dst[idx] = Iv[idx >> 7][idx & 127];
}

// ---------------- step B(t): trsm panels + M column t ----------------
// grid (9, 1, NS): r < rem -> trsm panel; r < rem+t -> M_tk; r == rem+t -> copy M_tt
__global__ __launch_bounds__(256) void step_b_kernel(int t) {
    int s = blockIdx.z;
    int r = blockIdx.x;
    int rem = NBLK - 1 - t;
    float* P = g_prec + (size_t)s * DD2;
    const float* Dv = g_Dinv + ((size_t)s * NBLK + t) * 16384;
    if (r < rem) {
        int i = t + 1 + r;
        float* Ablk = P + (size_t)i * 128 * DDIM + t * 128;
        gemmK<0, 1>(Ablk, DDIM, Dv, 128, Ablk, DDIM, 128, 1.0f, 0);
    } else if (r < rem + t) {
        int k = r - rem;
        const float* Stk = g_S + (size_t)s * DD2 + (size_t)t * 128 * DDIM + k * 128;
        float* Mtk = g_M + (size_t)s * DD2 + (size_t)t * 128 * DDIM + k * 128;
        gemmK<0, 0>(Dv, 128, Stk, DDIM, Mtk, DDIM, 128, -1.0f, 0);
    } else {
        float* Mtt = g_M + (size_t)s * DD2 + (size_t)t * 128 * DDIM + t * 128;
        for (int idx = threadIdx.x; idx < 16384; idx += 256)
            Mtt[(size_t)(idx >> 7) * DDIM + (idx & 127)] = Dv[idx];
    }
}

// ---------------- step C(t): syrk trailing + S accumulation ----------------
// grid (tri(rem) + rem*(t+1), 1, NS)
__global__ __launch_bounds__(256) void step_c_kernel(int t) {
    int s = blockIdx.z;
    int r = blockIdx.x;
    int rem = NBLK - 1 - t;
    int ntri = rem * (rem + 1) / 2;
    float* P = g_prec + (size_t)s * DD2;
    if (r < ntri) {
        int a = 0;
        while ((a + 1) * (a + 2) / 2 <= r) a++;
        int b = r - a * (a + 1) / 2;
        int i = t + 1 + a, j = t + 1 + b;
        const float* Aik = P + (size_t)i * 128 * DDIM + t * 128;
        const float* Ajk = P + (size_t)j * 128 * DDIM + t * 128;
        float* Cij = P + (size_t)i * 128 * DDIM + j * 128;
        gemmK<0, 1>(Aik, DDIM, Ajk, DDIM, Cij, DDIM, 128, -1.0f, 1);
    } else {
        int e = r - ntri;
        int i = t + 1 + e / (t + 1);
        int k = e % (t + 1);
        const float* Lit = P + (size_t)i * 128 * DDIM + t * 128;
        const float* Mtk = g_M + (size_t)s * DD2 + (size_t)t * 128 * DDIM + k * 128;
        float* Sik = g_S + (size_t)s * DD2 + (size_t)i * 128 * DDIM + k * 128;
        gemmK<0, 0>(Lit, DDIM, Mtk, DDIM, Sik, DDIM, 128, 1.0f, 1);
    }
}

// ---------------- solves: T = M*XLY + Z^T ; W = M^T*T ----------------
__global__ __launch_bounds__(256) void solve1_kernel(const float* __restrict__ Z) {
    int s = blockIdx.z, i = blockIdx.x, ct = blockIdx.y;  // grid (9, 4, NS)
    const float* A = g_M + (size_t)s * DD2 + (size_t)i * 128 * DDIM;
    const float* B = g_R + (size_t)s * DR + ct * 64;
    float* C = g_T + (size_t)s * DR + (size_t)i * 128 * NCOUT + ct * 64;
    const float* Zp = Z + (size_t)s * NCOUT * DDIM + (size_t)(ct * 64) * DDIM + i * 128;
    gemmK64<0>(A, DDIM, B, NCOUT, C, NCOUT, (i + 1) * 128, Zp);
}

__global__ __launch_bounds__(256) void solve2_kernel() {
    int s = blockIdx.z, i = blockIdx.x, ct = blockIdx.y;  // grid (9, 4, NS)
    const float* A = g_M + (size_t)s * DD2 + (size_t)i * 128 * DDIM + i * 128;
    const float* B = g_T + (size_t)s * DR + (size_t)i * 128 * NCOUT + ct * 64;
    float* C = g_R + (size_t)s * DR + (size_t)i * 128 * NCOUT + ct * 64;
    gemmK64<1>(A, DDIM, B, NCOUT, C, NCOUT, (NBLK - i) * 128, nullptr);
}

// ---------------- output + reductions ----------------
__global__ __launch_bounds__(256) void finalize_kernel(const float* __restrict__ Z,
                                                       float* __restrict__ outW) {
    __shared__ float red[256];
    size_t i = (size_t)blockIdx.x * 256 + threadIdx.x;
    int d = (int)(i % DDIM);
    size_t r = i / DDIM;
    int c = (int)(r % NCOUT);
    int s = (int)(r / NCOUT);
    float w = g_R[((size_t)s * DDIM + d) * NCOUT + c];
    outW[i] = w;
    float z = Z[i];
    red[threadIdx.x] = 0.5f * z * z - 0.5f * w * w;
    __syncthreads();
    for (int off = 128; off; off >>= 1) {
        if (threadIdx.x < off) red[threadIdx.x] += red[threadIdx.x + off];
        __syncthreads();
    }
    if (threadIdx.x == 0) g_part[blockIdx.x] = red[0];
}

__global__ __launch_bounds__(256) void logpq_kernel(float* __restrict__ outL) {
    __shared__ float red[256];
    int s = blockIdx.x;
    float acc = 0.0f;
    for (int i = threadIdx.x; i < 1152; i += 256) acc += g_part[s * 1152 + i];
    red[threadIdx.x] = acc;
    __syncthreads();
    for (int off = 128; off; off >>= 1) {
        if (threadIdx.x < off) red[threadIdx.x] += red[threadIdx.x + off];
        __syncthreads();
    }
    if (threadIdx.x == 0) {
        float ld = 0.0f;
        for (int k = 0; k < NBLK; k++) ld += g_logdet_part[s * NBLK + k];
        outL[s] = red[0] - 0.5f * (float)NCOUT * ld;
    }
}

// ---------------- launch ----------------
#define POTF2_SMEM ((2 * 128 * 129 + 3 * 32 * 33) * (int)sizeof(float))

extern "C" void kernel_launch(void* const* d_in, const int* in_sizes, int n_in,
                              void* d_out, int out_size) {
    const float* X  = (const float*)d_in[0];
    const float* u  = (const float*)d_in[1];
    const float* lp = (const float*)d_in[2];
    const float* Z  = (const float*)d_in[3];
    float* outW = (float*)d_out;
    float* outL = outW + (size_t)NS * NCOUT * DDIM;

    cudaFuncSetAttribute(potf2_kernel, cudaFuncAttributeMaxDynamicSharedMemorySize, POTF2_SMEM);
    cudaFuncSetAttribute(tc_gram_kernel, cudaFuncAttributeMaxDynamicSharedMemorySize, GRAM_SMEM);

    build_patches<<<147456, 256>>>(X, lp);
    build_yt<<<8192, 256>>>(u, lp);
    zero_s_kernel<<<(NS * DD2 / 4 + 255) / 256, 256>>>();
    tc_gram_kernel<<<dim3(63, NS), 256, GRAM_SMEM>>>();

    for (int t = 0; t < NBLK; t++) {
        potf2_kernel<<<148, 512, POTF2_SMEM>>>(t);
        step_b_kernel<<<dim3(NBLK, 1, NS), 256>>>(t);
        int rem = NBLK - 1 - t;
        int nc = rem * (rem + 1) / 2 + rem * (t + 1);
        if (nc > 0) step_c_kernel<<<dim3(nc, 1, NS), 256>>>(t);
    }

    solve1_kernel<<<dim3(NBLK, 4, NS), 256>>>(Z);
    solve2_kernel<<<dim3(NBLK, 4, NS), 256>>>();

    finalize_kernel<<<4608, 256>>>(Z, outW);
    logpq_kernel<<<NS, 256>>>(outL);
}

// round 12
// speedup vs baseline: 4.2716x; 1.0435x over previous
#include <cuda_runtime.h>
#include <cuda_bf16.h>
#include <math.h>
#include <stdint.h>

// ---------------- problem constants ----------------
#define NS     4
#define NBATCH 32
#define NCIN   128
#define NCOUT  256
#define HH     16
#define WW     16
#define DDIM   1152
#define NPIX   256
#define NCOLS  8192
#define NBLK   9
#define DD2    (DDIM * DDIM)
#define DR     (DDIM * NCOUT)

// ---------------- scratch ----------------
__device__ __nv_bfloat16 g_Phi[(size_t)NS * DDIM * NCOLS];
__device__ __nv_bfloat16 g_Plo[(size_t)NS * DDIM * NCOLS];
__device__ __nv_bfloat16 g_Yhi[(size_t)NCOUT * NCOLS];
__device__ __nv_bfloat16 g_Ylo[(size_t)NCOUT * NCOLS];
__device__ float g_prec[(size_t)NS * DD2];
__device__ float g_M   [(size_t)NS * DD2];
__device__ float g_S   [(size_t)NS * DD2];
__device__ float g_R   [(size_t)NS * DR];
__device__ float g_T   [(size_t)NS * DR];
__device__ float g_Dinv[(size_t)NS * NBLK * 128 * 128];
__device__ float g_logdet_part[NS * NBLK];
__device__ float g_part[NS * 1152];

// ---------------- helpers ----------------
__device__ __forceinline__ uint32_t smem_u32(const void* p) {
    uint32_t a;
    asm("{ .reg .u64 t; cvta.to.shared.u64 t, %1; cvt.u32.u64 %0, t; }" : "=r"(a) : "l"(p));
    return a;
}

#define CP_ASYNC16(dst, src) \
    asm volatile("cp.async.cg.shared.global [%0], [%1], 16;" :: "r"(dst), "l"(src) : "memory")
#define CP_COMMIT() asm volatile("cp.async.commit_group;" ::: "memory")
#define CP_WAIT1()  asm volatile("cp.async.wait_group 1;" ::: "memory")

#define LDMATRIX_X4(r0, r1, r2, r3, addr) \
    asm volatile("ldmatrix.sync.aligned.m8n8.x4.shared.b16 {%0,%1,%2,%3}, [%4];" \
        : "=r"(r0), "=r"(r1), "=r"(r2), "=r"(r3) : "r"(addr))

#define MMA16816(d, a, b0, b1) \
    asm volatile("mma.sync.aligned.m16n8k16.row.col.f32.bf16.bf16.f32 " \
        "{%0,%1,%2,%3}, {%4,%5,%6,%7}, {%8,%9}, {%0,%1,%2,%3};" \
        : "+f"((d)[0]), "+f"((d)[1]), "+f"((d)[2]), "+f"((d)[3]) \
        : "r"((a)[0]), "r"((a)[1]), "r"((a)[2]), "r"((a)[3]), "r"(b0), "r"(b1))

__device__ __forceinline__ uint32_t sw128(uint32_t off) {
    return off ^ ((off >> 3) & 0x70);
}

// ---------------- patch build (bf16 hi/lo) ----------------
__global__ __launch_bounds__(256) void build_patches(const float* __restrict__ X,
                                                     const float* __restrict__ lp) {
    size_t i = (size_t)blockIdx.x * 256 + threadIdx.x;
    int n = (int)(i % NCOLS);
    size_t r = i / NCOLS;
    int d = (int)(r % DDIM);
    int s = (int)(r / DDIM);
    int b = n >> 8;
    int p = n & 255;
    int y = p >> 4, x = p & 15;
    int cin = d / 9;
    int rem = d - cin * 9;
    int kh = rem / 3, kw = rem - kh * 3;
    int yy = y + kh - 1, xx = x + kw - 1;
    float v = 0.0f;
    if (yy >= 0 && yy < HH && xx >= 0 && xx < WW) {
        float sp = expf(0.5f * lp[b]);
        v = sp * X[((((size_t)s * NBATCH + b) * NCIN + cin) * HH + yy) * WW + xx];
    }
    __nv_bfloat16 hi = __float2bfloat16_rn(v);
    g_Phi[i] = hi;
    g_Plo[i] = __float2bfloat16_rn(v - __bfloat162float(hi));
}

__global__ __launch_bounds__(256) void build_yt(const float* __restrict__ u,
                                                const float* __restrict__ lp) {
    size_t i = (size_t)blockIdx.x * 256 + threadIdx.x;
    int n = (int)(i % NCOLS);
    int c = (int)(i / NCOLS);
    int b = n >> 8;
    int p = n & 255;
    float v = expf(0.5f * lp[b]) * u[((size_t)b * NCOUT + c) * NPIX + p];
    __nv_bfloat16 hi = __float2bfloat16_rn(v);
    g_Yhi[i] = hi;
    g_Ylo[i] = __float2bfloat16_rn(v - __bfloat162float(hi));
}

__global__ __launch_bounds__(256) void zero_s_kernel() {
    size_t i = (size_t)blockIdx.x * 256 + threadIdx.x;
    ((float4*)g_S)[i] = make_float4(0.f, 0.f, 0.f, 0.f);
}

// ---------------- warp-MMA Gram kernel (XLX lower tiles + XLY) ----------------
// K-chunk 32. Each buffer: A-combined [128 rows x (Ah 64B | Al 64B)] = 16KB,
// B-combined same = 16KB -> 32KB/buffer, x2 buffers = 64KB -> 2 CTAs/SM, 252 CTAs = 1 wave.
#define TILE_B 16384
#define BUF_B  32768
#define GRAM_SMEM (2 * BUF_B)

__global__ void __launch_bounds__(256, 2) tc_gram_kernel() {
    extern __shared__ char sm[];
    uint32_t smb = smem_u32(sm);
    int tid = threadIdx.x;
    int wid = tid >> 5, lid = tid & 31;
    int s = blockIdx.y;
    int t = blockIdx.x;

    const __nv_bfloat16 *Ah, *Al, *Bh, *Bl;
    float* C;
    int ldc;
    float prior;
    if (t < 45) {
        int bi = 0;
        while ((bi + 1) * (bi + 2) / 2 <= t) bi++;
        int bj = t - bi * (bi + 1) / 2;
        size_t ar = (size_t)(s * DDIM + bi * 128) * NCOLS;
        size_t br = (size_t)(s * DDIM + bj * 128) * NCOLS;
        Ah = g_Phi + ar; Al = g_Plo + ar;
        Bh = g_Phi + br; Bl = g_Plo + br;
        C = g_prec + (size_t)s * DD2 + (size_t)bi * 128 * DDIM + bj * 128;
        ldc = DDIM;
        prior = (bi == bj) ? 1.0f : 0.0f;
    } else {
        int u2 = t - 45;
        int bi = u2 >> 1, bj = u2 & 1;
        size_t ar = (size_t)(s * DDIM + bi * 128) * NCOLS;
        size_t br = (size_t)bj * 128 * NCOLS;
        Ah = g_Phi + ar; Al = g_Plo + ar;
        Bh = g_Yhi + br; Bl = g_Ylo + br;
        C = g_R + (size_t)s * DR + (size_t)bi * 128 * NCOUT + bj * 128;
        ldc = NCOUT;
        prior = 0.0f;
    }

    // per-thread load mapping: 4 x 16B chunks for A-combined, 4 for B-combined
    // idx = tid + j*256 over 1024 chunks: row = idx>>3, chunkpos = idx&7
    // chunkpos 0..3 -> hi cols (chunkpos*8), 4..7 -> lo cols ((chunkpos-4)*8)
    const __nv_bfloat16* srcA[4];
    const __nv_bfloat16* srcB[4];
    uint32_t lsw[4];
#pragma unroll
    for (int j = 0; j < 4; j++) {
        int idx = tid + j * 256;
        int row = idx >> 3;
        int cp = idx & 7;
        lsw[j] = sw128((uint32_t)(row * 128 + cp * 16));
        size_t go = (size_t)row * NCOLS + (cp & 3) * 8;
        srcA[j] = ((cp < 4) ? Ah : Al) + go;
        srcB[j] = ((cp < 4) ? Bh : Bl) + go;
    }

    float acc[2][8][4];
#pragma unroll
    for (int a = 0; a < 2; a++)
#pragma unroll
        for (int b = 0; b < 8; b++)
#pragma unroll
            for (int c = 0; c < 4; c++) acc[a][b][c] = 0.0f;

    int wm = (wid >> 1) * 32;
    int wn = (wid & 1) * 64;
    int l16 = lid & 15;
    int kseg16 = (lid >> 4) * 16;

    // prologue: chunk 0 into buf 0
    {
#pragma unroll
        for (int j = 0; j < 4; j++) CP_ASYNC16(smb + lsw[j], srcA[j]);
#pragma unroll
        for (int j = 0; j < 4; j++) CP_ASYNC16(smb + TILE_B + lsw[j], srcB[j]);
        CP_COMMIT();
    }

    for (int i = 0; i < 256; i++) {
        if (i + 1 < 256) {
            int k0 = (i + 1) * 32;
            uint32_t bb = smb + ((i + 1) & 1) * BUF_B;
#pragma unroll
            for (int j = 0; j < 4; j++) CP_ASYNC16(bb + lsw[j], srcA[j] + k0);
#pragma unroll
            for (int j = 0; j < 4; j++) CP_ASYNC16(bb + TILE_B + lsw[j], srcB[j] + k0);
        }
        CP_COMMIT();
        CP_WAIT1();
        __syncthreads();

        uint32_t base = smb + (i & 1) * BUF_B;
#pragma unroll
        for (int ks = 0; ks < 2; ks++) {
            int kb = ks * 32 + kseg16;
            uint32_t ah[2][4], al[2][4];
#pragma unroll
            for (int mb = 0; mb < 2; mb++) {
                uint32_t rb128 = (uint32_t)((wm + mb * 16 + l16) * 128);
                LDMATRIX_X4(ah[mb][0], ah[mb][1], ah[mb][2], ah[mb][3],
                            base + sw128(rb128 + kb));
                LDMATRIX_X4(al[mb][0], al[mb][1], al[mb][2], al[mb][3],
                            base + sw128(rb128 + kb + 64));
            }
#pragma unroll
            for (int nb = 0; nb < 4; nb++) {
                uint32_t bh[4], bl[4];
                uint32_t rb128 = (uint32_t)((wn + nb * 16 + l16) * 128);
                LDMATRIX_X4(bh[0], bh[1], bh[2], bh[3],
                            base + TILE_B + sw128(rb128 + kb));
                LDMATRIX_X4(bl[0], bl[1], bl[2], bl[3],
                            base + TILE_B + sw128(rb128 + kb + 64));
#pragma unroll
                for (int mb = 0; mb < 2; mb++)
#pragma unroll
                    for (int h = 0; h < 2; h++) {
                        int n8 = nb * 2 + h;
                        MMA16816(acc[mb][n8], ah[mb], bh[h], bh[h + 2]);
                        MMA16816(acc[mb][n8], ah[mb], bl[h], bl[h + 2]);
                        MMA16816(acc[mb][n8], al[mb], bh[h], bh[h + 2]);
                    }
            }
        }
        __syncthreads();
    }

    int tq = lid >> 2;
    int tc2 = (lid & 3) * 2;
#pragma unroll
    for (int mb = 0; mb < 2; mb++) {
#pragma unroll
        for (int n8 = 0; n8 < 8; n8++) {
            int col = wn + n8 * 8 + tc2;
            int row0 = wm + mb * 16 + tq;
            int row1 = row0 + 8;
            float c0 = acc[mb][n8][0], c1 = acc[mb][n8][1];
            float c2 = acc[mb][n8][2], c3 = acc[mb][n8][3];
            if (prior != 0.0f) {
                if (row0 == col) c0 += prior;
                if (row0 == col + 1) c1 += prior;
                if (row1 == col) c2 += prior;
                if (row1 == col + 1) c3 += prior;
            }
            *(float2*)&C[(size_t)row0 * ldc + col] = make_float2(c0, c1);
            *(float2*)&C[(size_t)row1 * ldc + col] = make_float2(c2, c3);
        }
    }
}

// ---------------- fp32 tile GEMM cores ----------------
__device__ __forceinline__ void mm_tile_compute(const float (*As)[128], const float (*Bs)[128],
                                                float acc[8][8], int tr, int tc) {
#pragma unroll
    for (int kk = 0; kk < 16; kk++) {
        float ra[8], rb[8];
        *(float4*)&ra[0] = *(const float4*)&As[kk][tr * 8];
        *(float4*)&ra[4] = *(const float4*)&As[kk][tr * 8 + 4];
        *(float4*)&rb[0] = *(const float4*)&Bs[kk][tc * 8];
        *(float4*)&rb[4] = *(const float4*)&Bs[kk][tc * 8 + 4];
#pragma unroll
        for (int a = 0; a < 8; a++)
#pragma unroll
            for (int b = 0; b < 8; b++)
                acc[a][b] = fmaf(ra[a], rb[b], acc[a][b]);
    }
}

template <int TA, int TB>
__device__ __forceinline__ void gemmK(const float* __restrict__ A, int lda,
                                      const float* __restrict__ Bp, int ldb,
                                      float* __restrict__ C, int ldc,
                                      int Kdim, float alpha, int beta) {
    __shared__ float As[16][128];
    __shared__ float Bs[16][128];
    float acc[8][8];
#pragma unroll
    for (int a = 0; a < 8; a++)
#pragma unroll
        for (int b = 0; b < 8; b++) acc[a][b] = 0.0f;
    int tid = threadIdx.x;
    int tr = tid >> 4, tc = tid & 15;

    for (int k0 = 0; k0 < Kdim; k0 += 16) {
#pragma unroll
        for (int q = 0; q < 2; q++) {
            int idx = tid + q * 256;
            if (TA) {
                int kk = idx >> 5, m4 = (idx & 31) << 2;
                float4 v = *(const float4*)&A[(size_t)(k0 + kk) * lda + m4];
                *(float4*)&As[kk][m4] = v;
            } else {
                int rr = idx >> 2, c4 = (idx & 3) << 2;
                float4 v = *(const float4*)&A[(size_t)rr * lda + k0 + c4];
                As[c4 + 0][rr] = v.x; As[c4 + 1][rr] = v.y;
                As[c4 + 2][rr] = v.z; As[c4 + 3][rr] = v.w;
            }
            if (TB) {
                int rr = idx >> 2, c4 = (idx & 3) << 2;
                float4 v = *(const float4*)&Bp[(size_t)rr * ldb + k0 + c4];
                Bs[c4 + 0][rr] = v.x; Bs[c4 + 1][rr] = v.y;
                Bs[c4 + 2][rr] = v.z; Bs[c4 + 3][rr] = v.w;
            } else {
                int kk = idx >> 5, m4 = (idx & 31) << 2;
                float4 v = *(const float4*)&Bp[(size_t)(k0 + kk) * ldb + m4];
                *(float4*)&Bs[kk][m4] = v;
            }
        }
        __syncthreads();
        mm_tile_compute(As, Bs, acc, tr, tc);
        __syncthreads();
    }
#pragma unroll
    for (int a = 0; a < 8; a++) {
        int row = tr * 8 + a;
#pragma unroll
        for (int b = 0; b < 8; b++) {
            int col = tc * 8 + b;
            float v = alpha * acc[a][b];
            if (beta) v += C[(size_t)row * ldc + col];
            C[(size_t)row * ldc + col] = v;
        }
    }
}

template <int TA>
__device__ __forceinline__ void gemmK64(const float* __restrict__ A, int lda,
                                        const float* __restrict__ Bp, int ldb,
                                        float* __restrict__ C, int ldc,
                                        int Kdim, const float* __restrict__ Zp) {
    __shared__ float As[16][128];
    __shared__ float Bs[16][64];
    float acc[8][4];
#pragma unroll
    for (int a = 0; a < 8; a++)
#pragma unroll
        for (int b = 0; b < 4; b++) acc[a][b] = 0.0f;
    int tid = threadIdx.x;
    int tr = tid >> 4, tc = tid & 15;

    for (int k0 = 0; k0 < Kdim; k0 += 16) {
#pragma unroll
        for (int q = 0; q < 2; q++) {
            int idx = tid + q * 256;
            if (TA) {
                int kk = idx >> 5, m4 = (idx & 31) << 2;
                float4 v = *(const float4*)&A[(size_t)(k0 + kk) * lda + m4];
                *(float4*)&As[kk][m4] = v;
            } else {
                int rr = idx >> 2, c4 = (idx & 3) << 2;
                float4 v = *(const float4*)&A[(size_t)rr * lda + k0 + c4];
                As[c4 + 0][rr] = v.x; As[c4 + 1][rr] = v.y;
                As[c4 + 2][rr] = v.z; As[c4 + 3][rr] = v.w;
            }
        }
        {
            int kk = tid >> 4, n4 = (tid & 15) << 2;
            float4 v = *(const float4*)&Bp[(size_t)(k0 + kk) * ldb + n4];
            *(float4*)&Bs[kk][n4] = v;
        }
        __syncthreads();
#pragma unroll
        for (int kk = 0; kk < 16; kk++) {
            float ra[8], rb[4];
            *(float4*)&ra[0] = *(const float4*)&As[kk][tr * 8];
            *(float4*)&ra[4] = *(const float4*)&As[kk][tr * 8 + 4];
            *(float4*)&rb[0] = *(const float4*)&Bs[kk][tc * 4];
#pragma unroll
            for (int a = 0; a < 8; a++)
#pragma unroll
                for (int b = 0; b < 4; b++)
                    acc[a][b] = fmaf(ra[a], rb[b], acc[a][b]);
        }
        __syncthreads();
    }
#pragma unroll
    for (int a = 0; a < 8; a++) {
        int row = tr * 8 + a;
        float4 v = make_float4(acc[a][0], acc[a][1], acc[a][2], acc[a][3]);
        if (Zp) {
            int col = tc * 4;
            v.x += Zp[(size_t)(col + 0) * DDIM + row];
            v.y += Zp[(size_t)(col + 1) * DDIM + row];
            v.z += Zp[(size_t)(col + 2) * DDIM + row];
            v.w += Zp[(size_t)(col + 3) * DDIM + row];
        }
        *(float4*)&C[(size_t)row * ldc + tc * 4] = v;
    }
}

// ---------------- Cholesky diag block ----------------
// p-loop deliberately NOT unrolled: the unrolled body was ~160KB of straight-line
// code and the single working warp paid cold-I$ misses through all of it.
__global__ __launch_bounds__(512) void potf2_kernel(int kb) {
    if (blockIdx.x >= NS) return;
    extern __shared__ float sh[];
    float (*Ls)[129] = (float(*)[129])sh;
    float (*Iv)[129] = (float(*)[129])(sh + 128 * 129);
    float (*Tbuf)[33] = (float(*)[33])(sh + 2 * 128 * 129);
    __shared__ float red[128];
    int s = blockIdx.x;
    int tid = threadIdx.x;
    float* Ablk = g_prec + (size_t)s * DD2 + (size_t)kb * 128 * DDIM + kb * 128;

    for (int idx = tid; idx < 128 * 128; idx += 512)
        Ls[idx >> 7][idx & 127] = Ablk[(size_t)(idx >> 7) * DDIM + (idx & 127)];
    for (int idx = tid; idx < 128 * 129; idx += 512)
        ((float*)Iv)[idx] = 0.0f;
    __syncthreads();

#pragma unroll 1
    for (int p = 0; p < 4; p++) {
        int c0 = p * 32;
        if (tid < 32) {
            int r = tid;
            float row[32];
#pragma unroll
            for (int j = 0; j < 32; j++) row[j] = Ls[c0 + r][c0 + j];
#pragma unroll
            for (int j = 0; j < 32; j++) {
                float d = __shfl_sync(0xffffffffu, row[j], j);
                float ljj = sqrtf(d);
                float inv = 1.0f / ljj;
                row[j] = (r == j) ? ljj : ((r > j) ? row[j] * inv : row[j]);
                float lrj = row[j];
#pragma unroll
                for (int c = j + 1; c < 32; c++) {
                    float lcj = __shfl_sync(0xffffffffu, row[j], c);
                    if (r >= c) row[c] -= lrj * lcj;
                }
            }
#pragma unroll
            for (int j = 0; j < 32; j++) Ls[c0 + r][c0 + j] = row[j];

            int c = r;
            float x[32];
#pragma unroll
            for (int i = 0; i < 32; i++) {
                float acc = (i == c) ? 1.0f : 0.0f;
#pragma unroll
                for (int t = 0; t < i; t++) {
                    float lit = __shfl_sync(0xffffffffu, row[t], i);
                    acc -= lit * x[t];
                }
                float lii = __shfl_sync(0xffffffffu, row[i], i);
                x[i] = acc * (1.0f / lii);
            }
#pragma unroll
            for (int i = 0; i < 32; i++) Iv[c0 + i][c0 + c] = x[i];
        }
        __syncthreads();

        if (p < 3) {
            const int base = c0 + 32;
            const int nrows = 128 - base;
            const int nout = nrows * 32;
            float vreg[6];
            int cnt = 0;
            for (int e = tid; e < nout; e += 512, cnt++) {
                int ri = base + (e >> 5);
                int c = e & 31;
                float acc = 0.0f;
#pragma unroll
                for (int t = 0; t < 32; t++)
                    acc += Ls[ri][c0 + t] * Iv[c0 + c][c0 + t];
                vreg[cnt] = acc;
            }
            __syncthreads();
            cnt = 0;
            for (int e = tid; e < nout; e += 512, cnt++)
                Ls[base + (e >> 5)][c0 + (e & 31)] = vreg[cnt];
            __syncthreads();
            const int tpr = nrows >> 2;
            const int ntile = tpr * tpr;
            for (int e = tid; e < ntile; e += 512) {
                int ti = e / tpr, tj = e - ti * tpr;
                int r0 = base + ti * 4, q0 = base + tj * 4;
                float accq[4][4];
#pragma unroll
                for (int a = 0; a < 4; a++)
#pragma unroll
                    for (int b = 0; b < 4; b++)
                        accq[a][b] = Ls[r0 + a][q0 + b];
#pragma unroll
                for (int t = 0; t < 32; t++) {
                    float av[4], bv[4];
#pragma unroll
                    for (int a = 0; a < 4; a++) av[a] = Ls[r0 + a][c0 + t];
#pragma unroll
                    for (int b = 0; b < 4; b++) bv[b] = Ls[q0 + b][c0 + t];
#pragma unroll
                    for (int a = 0; a < 4; a++)
#pragma unroll
                        for (int b = 0; b < 4; b++)
                            accq[a][b] -= av[a] * bv[b];
                }
#pragma unroll
                for (int a = 0; a < 4; a++)
#pragma unroll
                    for (int b = 0; b < 4; b++)
                        Ls[r0 + a][q0 + b] = accq[a][b];
            }
            __syncthreads();
        }
    }

    if (tid < 128) red[tid] = 2.0f * logf(Ls[tid][tid]);
    __syncthreads();
    for (int off = 64; off; off >>= 1) {
        if (tid < off) red[tid] += red[tid + off];
        __syncthreads();
    }
    if (tid == 0) g_logdet_part[s * NBLK + kb] = red[0];

    int grp = tid >> 7;
    int gt = tid & 127;
    int tr = gt >> 4;
    int tcg = gt & 15;
#pragma unroll 1
    for (int step = 1; step <= 3; step++) {
        int j = grp, i = grp + step;
        bool act = (i <= 3);
        if (act) {
            float acc[4][2];
#pragma unroll
            for (int a = 0; a < 4; a++) { acc[a][0] = 0.0f; acc[a][1] = 0.0f; }
            for (int t = j; t < i; t++) {
#pragma unroll 1
                for (int u = 0; u < 32; u++) {
                    float b0 = Iv[32 * t + u][32 * j + tcg * 2];
                    float b1 = Iv[32 * t + u][32 * j + tcg * 2 + 1];
#pragma unroll
                    for (int a = 0; a < 4; a++) {
                        float av = Ls[32 * i + tr * 4 + a][32 * t + u];
                        acc[a][0] += av * b0;
                        acc[a][1] += av * b1;
                    }
                }
            }
#pragma unroll
            for (int a = 0; a < 4; a++) {
                Tbuf[grp * 32 + tr * 4 + a][tcg * 2]     = acc[a][0];
                Tbuf[grp * 32 + tr * 4 + a][tcg * 2 + 1] = acc[a][1];
            }
        }
        __syncthreads();
        if (act) {
            float acc[4][2];
#pragma unroll
            for (int a = 0; a < 4; a++) { acc[a][0] = 0.0f; acc[a][1] = 0.0f; }
#pragma unroll 1
            for (int u = 0; u < 32; u++) {
                float b0 = Tbuf[grp * 32 + u][tcg * 2];
                float b1 = Tbuf[grp * 32 + u][tcg * 2 + 1];
#pragma unroll
                for (int a = 0; a < 4; a++) {
                    float av = Iv[32 * i + tr * 4 + a][32 * i + u];
                    acc[a][0] += av * b0;
                    acc[a][1] += av * b1;
                }
            }
#pragma unroll
            for (int a = 0; a < 4; a++) {
                Iv[32 * i + tr * 4 + a][32 * j + tcg * 2]     = -acc[a][0];
                Iv[32 * i + tr * 4 + a][32 * j + tcg * 2 + 1] = -acc[a][1];
            }
        }
        __syncthreads();
    }

    float* Dst = g_Dinv + ((size_t)s * NBLK + kb) * 16384;
    for (int idx = tid; idx < 128 * 128; idx += 512)
        Dst[idx] = Iv[idx >> 7][idx & 127];
}

// ---------------- step B(t): trsm panels + M column t ----------------
__global__ __launch_bounds__(256) void step_b_kernel(int t) {
    int s = blockIdx.z;
    int r = blockIdx.x;
    int rem = NBLK - 1 - t;
    float* P = g_prec + (size_t)s * DD2;
    const float* Dv = g_Dinv + ((size_t)s * NBLK + t) * 16384;
    if (r < rem) {
        int i = t + 1 + r;
        float* Ablk = P + (size_t)i * 128 * DDIM + t * 128;
        gemmK<0, 1>(Ablk, DDIM, Dv, 128, Ablk, DDIM, 128, 1.0f, 0);
    } else if (r < rem + t) {
        int k = r - rem;
        const float* Stk = g_S + (size_t)s * DD2 + (size_t)t * 128 * DDIM + k * 128;
        float* Mtk = g_M + (size_t)s * DD2 + (size_t)t * 128 * DDIM + k * 128;
        gemmK<0, 0>(Dv, 128, Stk, DDIM, Mtk, DDIM, 128, -1.0f, 0);
    } else {
        float* Mtt = g_M + (size_t)s * DD2 + (size_t)t * 128 * DDIM + t * 128;
        for (int idx = threadIdx.x; idx < 16384; idx += 256)
            Mtt[(size_t)(idx >> 7) * DDIM + (idx & 127)] = Dv[idx];
    }
}

// ---------------- step C(t): syrk trailing + S accumulation ----------------
__global__ __launch_bounds__(256) void step_c_kernel(int t) {
    int s = blockIdx.z;
    int r = blockIdx.x;
    int rem = NBLK - 1 - t;
    int ntri = rem * (rem + 1) / 2;
    float* P = g_prec + (size_t)s * DD2;
    if (r < ntri) {
        int a = 0;
        while ((a + 1) * (a + 2) / 2 <= r) a++;
        int b = r - a * (a + 1) / 2;
        int i = t + 1 + a, j = t + 1 + b;
        const float* Aik = P + (size_t)i * 128 * DDIM + t * 128;
        const float* Ajk = P + (size_t)j * 128 * DDIM + t * 128;
        float* Cij = P + (size_t)i * 128 * DDIM + j * 128;
        gemmK<0, 1>(Aik, DDIM, Ajk, DDIM, Cij, DDIM, 128, -1.0f, 1);
    } else {
        int e = r - ntri;
        int i = t + 1 + e / (t + 1);
        int k = e % (t + 1);
        const float* Lit = P + (size_t)i * 128 * DDIM + t * 128;
        const float* Mtk = g_M + (size_t)s * DD2 + (size_t)t * 128 * DDIM + k * 128;
        float* Sik = g_S + (size_t)s * DD2 + (size_t)i * 128 * DDIM + k * 128;
        gemmK<0, 0>(Lit, DDIM, Mtk, DDIM, Sik, DDIM, 128, 1.0f, 1);
    }
}

// ---------------- solves: T = M*XLY + Z^T ; W = M^T*T ----------------
__global__ __launch_bounds__(256) void solve1_kernel(const float* __restrict__ Z) {
    int s = blockIdx.z, i = blockIdx.x, ct = blockIdx.y;
    const float* A = g_M + (size_t)s * DD2 + (size_t)i * 128 * DDIM;
    const float* B = g_R + (size_t)s * DR + ct * 64;
    float* C = g_T + (size_t)s * DR + (size_t)i * 128 * NCOUT + ct * 64;
    const float* Zp = Z + (size_t)s * NCOUT * DDIM + (size_t)(ct * 64) * DDIM + i * 128;
    gemmK64<0>(A, DDIM, B, NCOUT, C, NCOUT, (i + 1) * 128, Zp);
}

__global__ __launch_bounds__(256) void solve2_kernel() {
    int s = blockIdx.z, i = blockIdx.x, ct = blockIdx.y;
    const float* A = g_M + (size_t)s * DD2 + (size_t)i * 128 * DDIM + i * 128;
    const float* B = g_T + (size_t)s * DR + (size_t)i * 128 * NCOUT + ct * 64;
    float* C = g_R + (size_t)s * DR + (size_t)i * 128 * NCOUT + ct * 64;
    gemmK64<1>(A, DDIM, B, NCOUT, C, NCOUT, (NBLK - i) * 128, nullptr);
}

// ---------------- output + reductions ----------------
__global__ __launch_bounds__(256) void finalize_kernel(const float* __restrict__ Z,
                                                       float* __restrict__ outW) {
    __shared__ float red[256];
    size_t i = (size_t)blockIdx.x * 256 + threadIdx.x;
    int d = (int)(i % DDIM);
    size_t r = i / DDIM;
    int c = (int)(r % NCOUT);
    int s = (int)(r / NCOUT);
    float w = g_R[((size_t)s * DDIM + d) * NCOUT + c];
    outW[i] = w;
    float z = Z[i];
    red[threadIdx.x] = 0.5f * z * z - 0.5f * w * w;
    __syncthreads();
    for (int off = 128; off; off >>= 1) {
        if (threadIdx.x < off) red[threadIdx.x] += red[threadIdx.x + off];
        __syncthreads();
    }
    if (threadIdx.x == 0) g_part[blockIdx.x] = red[0];
}

__global__ __launch_bounds__(256) void logpq_kernel(float* __restrict__ outL) {
    __shared__ float red[256];
    int s = blockIdx.x;
    float acc = 0.0f;
    for (int i = threadIdx.x; i < 1152; i += 256) acc += g_part[s * 1152 + i];
    red[threadIdx.x] = acc;
    __syncthreads();
    for (int off = 128; off; off >>= 1) {
        if (threadIdx.x < off) red[threadIdx.x] += red[threadIdx.x + off];
        __syncthreads();
    }
    if (threadIdx.x == 0) {
        float ld = 0.0f;
        for (int k = 0; k < NBLK; k++) ld += g_logdet_part[s * NBLK + k];
        outL[s] = red[0] - 0.5f * (float)NCOUT * ld;
    }
}

// ---------------- launch ----------------
#define POTF2_SMEM ((2 * 128 * 129 + 3 * 32 * 33) * (int)sizeof(float))

extern "C" void kernel_launch(void* const* d_in, const int* in_sizes, int n_in,
                              void* d_out, int out_size) {
    const float* X  = (const float*)d_in[0];
    const float* u  = (const float*)d_in[1];
    const float* lp = (const float*)d_in[2];
    const float* Z  = (const float*)d_in[3];
    float* outW = (float*)d_out;
    float* outL = outW + (size_t)NS * NCOUT * DDIM;

    cudaFuncSetAttribute(potf2_kernel, cudaFuncAttributeMaxDynamicSharedMemorySize, POTF2_SMEM);
    cudaFuncSetAttribute(tc_gram_kernel, cudaFuncAttributeMaxDynamicSharedMemorySize, GRAM_SMEM);

    build_patches<<<147456, 256>>>(X, lp);
    build_yt<<<8192, 256>>>(u, lp);
    zero_s_kernel<<<(NS * DD2 / 4 + 255) / 256, 256>>>();
    tc_gram_kernel<<<dim3(63, NS), 256, GRAM_SMEM>>>();

    for (int t = 0; t < NBLK; t++) {
        potf2_kernel<<<148, 512, POTF2_SMEM>>>(t);
        step_b_kernel<<<dim3(NBLK, 1, NS), 256>>>(t);
        int rem = NBLK - 1 - t;
        int nc = rem * (rem + 1) / 2 + rem * (t + 1);
        if (nc > 0) step_c_kernel<<<dim3(nc, 1, NS), 256>>>(t);
    }

    solve1_kernel<<<dim3(NBLK, 4, NS), 256>>>(Z);
    solve2_kernel<<<dim3(NBLK, 4, NS), 256>>>();

    finalize_kernel<<<4608, 256>>>(Z, outW);
    logpq_kernel<<<NS, 256>>>(outL);
}